// round 7
// baseline (speedup 1.0000x reference)
#include <cuda_runtime.h>
#include <cuda_bf16.h>
#include <math.h>
#include <stdint.h>

#define BB 2
#define SS 2048
#define DD 1024
#define HH 16
#define DH 64
#define BH (BB*HH)          // 32
#define MROWS (BB*SS)       // 4096
#define NROWTOT (BH*SS)     // 65536 score rows

// Scratch (device globals: allocation-free)
__device__ float  g_Q[BH * SS * DH];
__device__ float  g_K[BH * SS * DH];
__device__ float  g_V[BH * SS * DH];
__device__ float  g_Ctx[MROWS * DD];
__device__ float2 g_Part[(size_t)NROWTOT * 16];   // per-row per-colblock (max, expsum)
__device__ float2 g_Stats[NROWTOT];               // per-row (max, 1/sum)

__device__ __forceinline__ float to_tf32(float x) {
    uint32_t u;
    asm("cvt.rna.tf32.f32 %0, %1;" : "=r"(u) : "f"(x));
    return __uint_as_float(u);
}
__device__ __forceinline__ uint32_t cvt_u(float x) {
    uint32_t u;
    asm("cvt.rna.tf32.f32 %0, %1;" : "=r"(u) : "f"(x));
    return u;
}

#define MMA_TF32(c, a, b)                                                     \
    asm volatile(                                                             \
        "mma.sync.aligned.m16n8k8.row.col.f32.tf32.tf32.f32 "                 \
        "{%0,%1,%2,%3},{%4,%5,%6,%7},{%8,%9},{%0,%1,%2,%3};\n"                \
        : "+f"(c[0]), "+f"(c[1]), "+f"(c[2]), "+f"(c[3])                      \
        : "r"(a[0]), "r"(a[1]), "r"(a[2]), "r"(a[3]), "r"(b[0]), "r"(b[1]))

#define CP16(dst_u32, src_ptr)                                                \
    asm volatile("cp.async.ca.shared.global [%0], [%1], 16;\n"                \
                 :: "r"(dst_u32), "l"(src_ptr))

__device__ __forceinline__ void sm_merge(float& m, float& s, float om, float os) {
    float M = fmaxf(m, om);
    float e1 = (m  > -INFINITY) ? __expf(m  - M) : 0.0f;
    float e2 = (om > -INFINITY) ? __expf(om - M) : 0.0f;
    s = s * e1 + os * e2;
    m = M;
}

struct ProjArgs {
    const float* A[3];
    const float* W[3];
    const float* bias[3];
    float* C[3];
};

// ---------------------------------------------------------------------------
// TF32 MMA GEMM with cp.async 2-stage pipeline: C = A*B^T + bias.
// BM=BN=128, BK=32, 256 thr, warp tile 64x32.
// MODE 0: proj (z-indexed q/k/v, scatter to [B,H,S,DH])
// MODE 1: dense (row-major)
// ---------------------------------------------------------------------------
template<int MODE>
__global__ __launch_bounds__(256, 2)
void mma_nt(ProjArgs pa)
{
    extern __shared__ float sm[];
    float* pA = sm;               // 2 stages x 128x36
    float* pB = sm + 2 * 4608;

    const int zi = (MODE == 0) ? blockIdx.z : 0;
    const float* A    = pa.A[zi];
    const float* Bw   = pa.W[zi];
    const float* bias = pa.bias[zi];
    float* C          = pa.C[zi];

    const int tid = threadIdx.x;
    const int wid = tid >> 5, lane = tid & 31;
    const int g = lane >> 2, q = lane & 3;
    const int wm0 = (wid >> 2) * 64;
    const int wn0 = (wid & 3) * 32;
    const int row0 = blockIdx.y * 128;
    const int col0 = blockIdx.x * 128;
    const int K = DD;

    uint32_t sA = (uint32_t)__cvta_generic_to_shared(pA);
    uint32_t sB = (uint32_t)__cvta_generic_to_shared(pB);

    float acc[4][4][4];
    #pragma unroll
    for (int i = 0; i < 4; ++i)
        #pragma unroll
        for (int j = 0; j < 4; ++j)
            #pragma unroll
            for (int r = 0; r < 4; ++r) acc[i][j][r] = 0.0f;

    auto copy_tile = [&](int st, int kt) {
        #pragma unroll
        for (int it = 0; it < 4; ++it) {
            const int idx = tid + it * 256;
            const int r = idx >> 3, c4 = (idx & 7) << 2;
            CP16(sA + (uint32_t)(st * 4608 + r * 36 + c4) * 4,
                 &A[(size_t)(row0 + r) * K + kt + c4]);
            CP16(sB + (uint32_t)(st * 4608 + r * 36 + c4) * 4,
                 &Bw[(size_t)(col0 + r) * K + kt + c4]);
        }
        asm volatile("cp.async.commit_group;\n");
    };

    copy_tile(0, 0);
    const int T = K / 32;
    for (int t = 0; t < T; ++t) {
        if (t + 1 < T) {
            copy_tile((t + 1) & 1, (t + 1) * 32);
            asm volatile("cp.async.wait_group 1;\n");
        } else {
            asm volatile("cp.async.wait_group 0;\n");
        }
        __syncthreads();
        const float* Asb = pA + (t & 1) * 4608;
        const float* Bsb = pB + (t & 1) * 4608;
        #pragma unroll
        for (int kk = 0; kk < 4; ++kk) {
            const int kb = kk * 8;
            uint32_t a[4][4], b[4][2];
            #pragma unroll
            for (int i = 0; i < 4; ++i) {
                a[i][0] = cvt_u(Asb[(wm0 + 16*i + g    ) * 36 + kb + q    ]);
                a[i][1] = cvt_u(Asb[(wm0 + 16*i + g + 8) * 36 + kb + q    ]);
                a[i][2] = cvt_u(Asb[(wm0 + 16*i + g    ) * 36 + kb + q + 4]);
                a[i][3] = cvt_u(Asb[(wm0 + 16*i + g + 8) * 36 + kb + q + 4]);
            }
            #pragma unroll
            for (int j = 0; j < 4; ++j) {
                b[j][0] = cvt_u(Bsb[(wn0 + 8*j + g) * 36 + kb + q    ]);
                b[j][1] = cvt_u(Bsb[(wn0 + 8*j + g) * 36 + kb + q + 4]);
            }
            #pragma unroll
            for (int i = 0; i < 4; ++i)
                #pragma unroll
                for (int j = 0; j < 4; ++j)
                    MMA_TF32(acc[i][j], a[i], b[j]);
        }
        __syncthreads();
    }

    #pragma unroll
    for (int i = 0; i < 4; ++i) {
        #pragma unroll
        for (int rr = 0; rr < 2; ++rr) {
            const int gr = row0 + wm0 + 16*i + g + rr*8;
            #pragma unroll
            for (int j = 0; j < 4; ++j) {
                const int gc = col0 + wn0 + 8*j + 2*q;
                const float v0 = acc[i][j][rr*2 + 0];
                const float v1 = acc[i][j][rr*2 + 1];
                float2 bv = *(const float2*)&bias[gc];
                if (MODE == 0) {
                    const int b = gr >> 11, s = gr & 2047;
                    const int h = gc >> 6, d = gc & 63;
                    *(float2*)&C[(((size_t)(b*HH + h))*SS + s)*DH + d] =
                        make_float2(v0 + bv.x, v1 + bv.y);
                } else {
                    *(float2*)&C[(size_t)gr * DD + gc] =
                        make_float2(v0 + bv.x, v1 + bv.y);
                }
            }
        }
    }
}

// ---------------------------------------------------------------------------
// Scores: per z: S = Q@K^T * 0.125, masked -> raw into weights region.
// Single BK=64 slab (K=DH). Fragments staged through smem; epilogue does
// coalesced mask/write and per-row (max, expsum) partials into g_Part.
// smem: As/Bs 2x(128x68) = 17408 floats, reused as W tile 128x132 = 16896.
// ---------------------------------------------------------------------------
__global__ __launch_bounds__(256, 2)
void scores_kernel(const float* __restrict__ Q, const float* __restrict__ Kh,
                   const int* __restrict__ maskAll, float* __restrict__ Wraw,
                   float2* __restrict__ Part)
{
    extern __shared__ float sm[];
    float* As = sm;            // 128 x 68
    float* Bs = sm + 8704;     // 128 x 68
    float* sW = sm;            // reused: 128 x 132

    const int tid = threadIdx.x;
    const int wid = tid >> 5, lane = tid & 31;
    const int g = lane >> 2, q = lane & 3;
    const int wm0 = (wid >> 2) * 64;
    const int wn0 = (wid & 3) * 32;
    const int z = blockIdx.z;
    const int row0 = blockIdx.y * 128;
    const int col0 = blockIdx.x * 128;

    const float* Qz = Q  + (size_t)z * SS * DH;
    const float* Kz = Kh + (size_t)z * SS * DH;
    float* Cz = Wraw + (size_t)z * SS * SS;
    const int* mask = maskAll + (size_t)(z / HH) * SS * SS;

    #pragma unroll
    for (int it = 0; it < 8; ++it) {
        const int idx = tid + it * 256;
        const int r = idx >> 4, c4 = (idx & 15) << 2;
        float4 va = *(const float4*)&Qz[(size_t)(row0 + r) * DH + c4];
        *(float4*)&As[r * 68 + c4] = make_float4(to_tf32(va.x), to_tf32(va.y),
                                                 to_tf32(va.z), to_tf32(va.w));
        float4 vb = *(const float4*)&Kz[(size_t)(col0 + r) * DH + c4];
        *(float4*)&Bs[r * 68 + c4] = make_float4(to_tf32(vb.x), to_tf32(vb.y),
                                                 to_tf32(vb.z), to_tf32(vb.w));
    }
    __syncthreads();

    float acc[4][4][4];
    #pragma unroll
    for (int i = 0; i < 4; ++i)
        #pragma unroll
        for (int j = 0; j < 4; ++j)
            #pragma unroll
            for (int r = 0; r < 4; ++r) acc[i][j][r] = 0.0f;

    #pragma unroll
    for (int kk = 0; kk < 8; ++kk) {
        const int kb = kk * 8;
        uint32_t a[4][4], b[4][2];
        #pragma unroll
        for (int i = 0; i < 4; ++i) {
            a[i][0] = __float_as_uint(As[(wm0 + 16*i + g    ) * 68 + kb + q    ]);
            a[i][1] = __float_as_uint(As[(wm0 + 16*i + g + 8) * 68 + kb + q    ]);
            a[i][2] = __float_as_uint(As[(wm0 + 16*i + g    ) * 68 + kb + q + 4]);
            a[i][3] = __float_as_uint(As[(wm0 + 16*i + g + 8) * 68 + kb + q + 4]);
        }
        #pragma unroll
        for (int j = 0; j < 4; ++j) {
            b[j][0] = __float_as_uint(Bs[(wn0 + 8*j + g) * 68 + kb + q    ]);
            b[j][1] = __float_as_uint(Bs[(wn0 + 8*j + g) * 68 + kb + q + 4]);
        }
        #pragma unroll
        for (int i = 0; i < 4; ++i)
            #pragma unroll
            for (int j = 0; j < 4; ++j)
                MMA_TF32(acc[i][j], a[i], b[j]);
    }
    __syncthreads();   // all warps done reading As/Bs -> safe to reuse as sW

    // fragments -> smem tile (scaled)
    #pragma unroll
    for (int i = 0; i < 4; ++i) {
        #pragma unroll
        for (int rr = 0; rr < 2; ++rr) {
            const int R = wm0 + 16*i + g + rr*8;
            #pragma unroll
            for (int j = 0; j < 4; ++j) {
                const int c = wn0 + 8*j + 2*q;
                *(float2*)&sW[R * 132 + c] =
                    make_float2(acc[i][j][rr*2] * 0.125f, acc[i][j][rr*2+1] * 0.125f);
            }
        }
    }
    __syncthreads();

    // Epilogue: thread owns half a row (64 floats). Coalesced mask read +
    // gmem write; in-thread online (max, expsum).
    {
        const int r    = tid >> 1;          // 0..127
        const int half = tid & 1;           // 0..1
        const int gr   = row0 + r;
        const int cbase = half * 64;
        const float* wrow = &sW[r * 132 + cbase];
        const int*  mrow = &mask[(size_t)gr * SS + col0 + cbase];
        float*      orow = &Cz[(size_t)gr * SS + col0 + cbase];

        float m = -INFINITY, s = 0.0f;
        #pragma unroll
        for (int i = 0; i < 16; ++i) {
            float4 v = *(const float4*)&wrow[i * 4];
            int4  mv = *(const int4*)&mrow[i * 4];
            v.x = mv.x ? v.x : -INFINITY;
            v.y = mv.y ? v.y : -INFINITY;
            v.z = mv.z ? v.z : -INFINITY;
            v.w = mv.w ? v.w : -INFINITY;
            *(float4*)&orow[i * 4] = v;
            float vm = fmaxf(fmaxf(v.x, v.y), fmaxf(v.z, v.w));
            if (vm > -INFINITY) {
                float Mn = fmaxf(m, vm);
                float keep = (m > -INFINITY) ? s * __expf(m - Mn) : 0.0f;
                float add = 0.0f;
                add += (v.x > -INFINITY) ? __expf(v.x - Mn) : 0.0f;
                add += (v.y > -INFINITY) ? __expf(v.y - Mn) : 0.0f;
                add += (v.z > -INFINITY) ? __expf(v.z - Mn) : 0.0f;
                add += (v.w > -INFINITY) ? __expf(v.w - Mn) : 0.0f;
                s = keep + add;
                m = Mn;
            }
        }
        // merge the two halves (adjacent lanes)
        float om = __shfl_xor_sync(0xffffffffu, m, 1);
        float os = __shfl_xor_sync(0xffffffffu, s, 1);
        sm_merge(m, s, om, os);
        if (half == 0)
            Part[((size_t)z * SS + gr) * 16 + blockIdx.x] = make_float2(m, s);
    }
}

// ---------------------------------------------------------------------------
// Reduce partials -> per-row (max, 1/sum)
// ---------------------------------------------------------------------------
__global__ __launch_bounds__(256)
void reduce_stats(const float2* __restrict__ Part, float2* __restrict__ Stats)
{
    const int row = blockIdx.x * 256 + threadIdx.x;
    float2 p[16];
    #pragma unroll
    for (int i = 0; i < 16; ++i) p[i] = Part[(size_t)row * 16 + i];
    float M = -INFINITY;
    #pragma unroll
    for (int i = 0; i < 16; ++i) M = fmaxf(M, p[i].x);
    float S = 0.0f;
    #pragma unroll
    for (int i = 0; i < 16; ++i)
        S += (p[i].x > -INFINITY) ? p[i].y * __expf(p[i].x - M) : 0.0f;
    Stats[row] = make_float2(M, (S > 0.0f) ? 1.0f / S : 0.0f);
}

// ---------------------------------------------------------------------------
// AV fused with softmax-apply: reads raw scores, computes w=exp(x-M)*invS,
// writes normalized weights IN PLACE (final output; per-thread RMW of its
// own addresses -> race-free), and accumulates W@V.
// BM=128, BK=32, reg-staged double buffer, warp tile 32x32.
// ---------------------------------------------------------------------------
__global__ __launch_bounds__(256, 2)
void mma_av(float* __restrict__ Wts, const float* __restrict__ Vh,
            const float2* __restrict__ Stats, float* __restrict__ Ctx)
{
    __shared__ float As[2][128][36];
    __shared__ float Bs[2][32][68];
    __shared__ float sM[128], sI[128];

    const int z = blockIdx.y;
    float* Aw = Wts + (size_t)z * SS * SS;
    const float* Vv = Vh + (size_t)z * SS * DH;
    const int row0 = blockIdx.x * 128;

    const int tid = threadIdx.x;
    const int wid = tid >> 5, lane = tid & 31;
    const int g = lane >> 2, q = lane & 3;
    const int wm0 = (wid >> 1) * 32;
    const int wn0 = (wid & 1) * 32;

    if (tid < 128) {
        float2 st = Stats[(size_t)z * SS + row0 + tid];
        sM[tid] = st.x; sI[tid] = st.y;
    }

    float acc[2][4][4];
    #pragma unroll
    for (int i = 0; i < 2; ++i)
        #pragma unroll
        for (int j = 0; j < 4; ++j)
            #pragma unroll
            for (int r = 0; r < 4; ++r) acc[i][j][r] = 0.0f;

    float4 ra[4], rb[2];
    #pragma unroll
    for (int it = 0; it < 4; ++it) {
        const int idx = tid + it * 256;
        const int r = idx >> 3, c4 = (idx & 7) << 2;
        ra[it] = *(const float4*)&Aw[(size_t)(row0 + r) * SS + c4];
    }
    #pragma unroll
    for (int it = 0; it < 2; ++it) {
        const int idx = tid + it * 256;
        const int r = idx >> 4, c4 = (idx & 15) << 2;
        rb[it] = *(const float4*)&Vv[(size_t)r * DH + c4];
    }
    __syncthreads();   // stats visible

    for (int t = 0; t < SS / 32; ++t) {
        const int kt = t * 32;
        const int st = t & 1;
        #pragma unroll
        for (int it = 0; it < 4; ++it) {
            const int idx = tid + it * 256;
            const int r = idx >> 3, c4 = (idx & 7) << 2;
            const float M = sM[r], I = sI[r];
            float4 w;
            w.x = __expf(ra[it].x - M) * I;
            w.y = __expf(ra[it].y - M) * I;
            w.z = __expf(ra[it].z - M) * I;
            w.w = __expf(ra[it].w - M) * I;
            *(float4*)&Aw[(size_t)(row0 + r) * SS + kt + c4] = w;   // final weights
            *(float4*)&As[st][r][c4] = make_float4(to_tf32(w.x), to_tf32(w.y),
                                                   to_tf32(w.z), to_tf32(w.w));
        }
        #pragma unroll
        for (int it = 0; it < 2; ++it) {
            const int idx = tid + it * 256;
            const int r = idx >> 4, c4 = (idx & 15) << 2;
            *(float4*)&Bs[st][r][c4] = make_float4(to_tf32(rb[it].x), to_tf32(rb[it].y),
                                                   to_tf32(rb[it].z), to_tf32(rb[it].w));
        }
        __syncthreads();
        if (t + 1 < SS / 32) {
            const int kt2 = kt + 32;
            #pragma unroll
            for (int it = 0; it < 4; ++it) {
                const int idx = tid + it * 256;
                const int r = idx >> 3, c4 = (idx & 7) << 2;
                ra[it] = *(const float4*)&Aw[(size_t)(row0 + r) * SS + kt2 + c4];
            }
            #pragma unroll
            for (int it = 0; it < 2; ++it) {
                const int idx = tid + it * 256;
                const int r = idx >> 4, c4 = (idx & 15) << 2;
                rb[it] = *(const float4*)&Vv[(size_t)(kt2 + r) * DH + c4];
            }
        }
        #pragma unroll
        for (int kk = 0; kk < 4; ++kk) {
            const int kb = kk * 8;
            uint32_t a[2][4], b[4][2];
            #pragma unroll
            for (int i = 0; i < 2; ++i) {
                a[i][0] = __float_as_uint(As[st][wm0 + 16*i + g    ][kb + q    ]);
                a[i][1] = __float_as_uint(As[st][wm0 + 16*i + g + 8][kb + q    ]);
                a[i][2] = __float_as_uint(As[st][wm0 + 16*i + g    ][kb + q + 4]);
                a[i][3] = __float_as_uint(As[st][wm0 + 16*i + g + 8][kb + q + 4]);
            }
            #pragma unroll
            for (int j = 0; j < 4; ++j) {
                b[j][0] = __float_as_uint(Bs[st][kb + q    ][wn0 + 8*j + g]);
                b[j][1] = __float_as_uint(Bs[st][kb + q + 4][wn0 + 8*j + g]);
            }
            #pragma unroll
            for (int i = 0; i < 2; ++i)
                #pragma unroll
                for (int j = 0; j < 4; ++j)
                    MMA_TF32(acc[i][j], a[i], b[j]);
        }
    }

    const int b = z / HH, h = z % HH;
    #pragma unroll
    for (int i = 0; i < 2; ++i) {
        #pragma unroll
        for (int rr = 0; rr < 2; ++rr) {
            const int s = row0 + wm0 + 16*i + g + rr*8;
            #pragma unroll
            for (int j = 0; j < 4; ++j) {
                const int n = wn0 + 8*j + 2*q;
                *(float2*)&Ctx[((size_t)(b*SS + s))*DD + h*64 + n] =
                    make_float2(acc[i][j][rr*2], acc[i][j][rr*2 + 1]);
            }
        }
    }
}

// ---------------------------------------------------------------------------
extern "C" void kernel_launch(void* const* d_in, const int* in_sizes, int n_in,
                              void* d_out, int out_size)
{
    const float* q       = (const float*)d_in[0];
    const float* k       = (const float*)d_in[1];
    const float* v       = (const float*)d_in[2];
    const int*   mask    = (const int*)d_in[3];
    const float* wq_w    = (const float*)d_in[4];
    const float* wq_b    = (const float*)d_in[5];
    const float* wk_w    = (const float*)d_in[6];
    const float* wk_b    = (const float*)d_in[7];
    const float* wv_w    = (const float*)d_in[8];
    const float* wv_b    = (const float*)d_in[9];
    const float* dense_w = (const float*)d_in[10];
    const float* dense_b = (const float*)d_in[11];

    float* out = (float*)d_out;
    float* wts = out + (size_t)BB * SS * DD;

    void *pQ, *pK, *pV, *pC, *pP, *pS;
    cudaGetSymbolAddress(&pQ, g_Q);
    cudaGetSymbolAddress(&pK, g_K);
    cudaGetSymbolAddress(&pV, g_V);
    cudaGetSymbolAddress(&pC, g_Ctx);
    cudaGetSymbolAddress(&pP, g_Part);
    cudaGetSymbolAddress(&pS, g_Stats);
    float*  gQ = (float*)pQ;
    float*  gK = (float*)pK;
    float*  gV = (float*)pV;
    float*  gC = (float*)pC;
    float2* gP = (float2*)pP;
    float2* gS = (float2*)pS;

    const int SM_GEMM = 73728;
    const int SM_SC   = 73728;
    static int inited = 0;
    if (!inited) {
        cudaFuncSetAttribute(mma_nt<0>, cudaFuncAttributeMaxDynamicSharedMemorySize, SM_GEMM);
        cudaFuncSetAttribute(mma_nt<1>, cudaFuncAttributeMaxDynamicSharedMemorySize, SM_GEMM);
        cudaFuncSetAttribute(scores_kernel, cudaFuncAttributeMaxDynamicSharedMemorySize, SM_SC);
        inited = 1;
    }

    const dim3 blk(256);

    // 1) QKV projections, one z=3 launch
    ProjArgs pa;
    pa.A[0] = q;    pa.W[0] = wq_w;    pa.bias[0] = wq_b;    pa.C[0] = gQ;
    pa.A[1] = k;    pa.W[1] = wk_w;    pa.bias[1] = wk_b;    pa.C[1] = gK;
    pa.A[2] = v;    pa.W[2] = wv_w;    pa.bias[2] = wv_b;    pa.C[2] = gV;
    const dim3 gproj(DD / 128, MROWS / 128, 3);       // (8, 32, 3)
    mma_nt<0><<<gproj, blk, SM_GEMM>>>(pa);

    // 2) Scores -> raw weights region + partials
    const dim3 gsc(SS / 128, SS / 128, BH);           // (16, 16, 32)
    scores_kernel<<<gsc, blk, SM_SC>>>(gQ, gK, mask, wts, gP);

    // 3) Per-row stats
    reduce_stats<<<NROWTOT / 256, 256>>>(gP, gS);

    // 4) AV + in-place normalize
    const dim3 gav(SS / 128, BH, 1);                  // (16, 32)
    mma_av<<<gav, blk>>>(wts, gV, gS, gC);

    // 5) Dense
    ProjArgs da;
    da.A[0] = gC;   da.W[0] = dense_w; da.bias[0] = dense_b; da.C[0] = out;
    da.A[1] = da.A[2] = nullptr; da.W[1] = da.W[2] = nullptr;
    da.bias[1] = da.bias[2] = nullptr; da.C[1] = da.C[2] = nullptr;
    const dim3 gd(DD / 128, MROWS / 128, 1);
    mma_nt<1><<<gd, blk, SM_GEMM>>>(da);
}

// round 8
// speedup vs baseline: 1.2166x; 1.2166x over previous
#include <cuda_runtime.h>
#include <cuda_bf16.h>
#include <math.h>
#include <stdint.h>

#define BB 2
#define SS 2048
#define DD 1024
#define HH 16
#define DH 64
#define BH (BB*HH)          // 32
#define MROWS (BB*SS)       // 4096
#define NROWTOT (BH*SS)     // 65536 score rows

// Scratch (device globals: allocation-free)
__device__ float  g_Q[BH * SS * DH];
__device__ float  g_K[BH * SS * DH];
__device__ float  g_V[BH * SS * DH];
__device__ float  g_Ctx[MROWS * DD];
__device__ float2 g_Part[(size_t)NROWTOT * 16];   // per-row per-colblock (max, expsum)
__device__ float2 g_Stats[NROWTOT];               // per-row (max, 1/sum)

__device__ __forceinline__ float to_tf32(float x) {
    uint32_t u;
    asm("cvt.rna.tf32.f32 %0, %1;" : "=r"(u) : "f"(x));
    return __uint_as_float(u);
}
__device__ __forceinline__ uint32_t cvt_u(float x) {
    uint32_t u;
    asm("cvt.rna.tf32.f32 %0, %1;" : "=r"(u) : "f"(x));
    return u;
}

#define MMA_TF32(c, a, b)                                                     \
    asm volatile(                                                             \
        "mma.sync.aligned.m16n8k8.row.col.f32.tf32.tf32.f32 "                 \
        "{%0,%1,%2,%3},{%4,%5,%6,%7},{%8,%9},{%0,%1,%2,%3};\n"                \
        : "+f"(c[0]), "+f"(c[1]), "+f"(c[2]), "+f"(c[3])                      \
        : "r"(a[0]), "r"(a[1]), "r"(a[2]), "r"(a[3]), "r"(b[0]), "r"(b[1]))

#define CP16(dst_u32, src_ptr)                                                \
    asm volatile("cp.async.ca.shared.global [%0], [%1], 16;\n"                \
                 :: "r"(dst_u32), "l"(src_ptr))

__device__ __forceinline__ void sm_merge(float& m, float& s, float om, float os) {
    float M = fmaxf(m, om);
    float e1 = (m  > -INFINITY) ? __expf(m  - M) : 0.0f;
    float e2 = (om > -INFINITY) ? __expf(om - M) : 0.0f;
    s = s * e1 + os * e2;
    m = M;
}

// ---------------------------------------------------------------------------
// TF32 MMA GEMM with cp.async 2-stage pipeline: C = A*B^T + bias.
// A[M,1024] rm, B[N,1024] rm. BM=BN=128, BK=32, 256 thr, warp tile 64x32.
// MODE 0: proj (scatter to [B,H,S,DH]) | MODE 1: dense (row-major)
// ---------------------------------------------------------------------------
template<int MODE>
__global__ __launch_bounds__(256, 2)
void mma_nt(const float* __restrict__ A, const float* __restrict__ Bw,
            const float* __restrict__ bias, float* __restrict__ C)
{
    extern __shared__ float sm[];
    float* pA = sm;               // 2 stages x 128x36
    float* pB = sm + 2 * 4608;

    const int tid = threadIdx.x;
    const int wid = tid >> 5, lane = tid & 31;
    const int g = lane >> 2, q = lane & 3;
    const int wm0 = (wid >> 2) * 64;
    const int wn0 = (wid & 3) * 32;
    const int row0 = blockIdx.y * 128;
    const int col0 = blockIdx.x * 128;
    const int K = DD;

    uint32_t sA = (uint32_t)__cvta_generic_to_shared(pA);
    uint32_t sB = (uint32_t)__cvta_generic_to_shared(pB);

    float acc[4][4][4];
    #pragma unroll
    for (int i = 0; i < 4; ++i)
        #pragma unroll
        for (int j = 0; j < 4; ++j)
            #pragma unroll
            for (int r = 0; r < 4; ++r) acc[i][j][r] = 0.0f;

    auto copy_tile = [&](int st, int kt) {
        #pragma unroll
        for (int it = 0; it < 4; ++it) {
            const int idx = tid + it * 256;
            const int r = idx >> 3, c4 = (idx & 7) << 2;
            CP16(sA + (uint32_t)(st * 4608 + r * 36 + c4) * 4,
                 &A[(size_t)(row0 + r) * K + kt + c4]);
            CP16(sB + (uint32_t)(st * 4608 + r * 36 + c4) * 4,
                 &Bw[(size_t)(col0 + r) * K + kt + c4]);
        }
        asm volatile("cp.async.commit_group;\n");
    };

    copy_tile(0, 0);
    const int T = K / 32;
    for (int t = 0; t < T; ++t) {
        if (t + 1 < T) {
            copy_tile((t + 1) & 1, (t + 1) * 32);
            asm volatile("cp.async.wait_group 1;\n");
        } else {
            asm volatile("cp.async.wait_group 0;\n");
        }
        __syncthreads();
        const float* Asb = pA + (t & 1) * 4608;
        const float* Bsb = pB + (t & 1) * 4608;
        #pragma unroll
        for (int kk = 0; kk < 4; ++kk) {
            const int kb = kk * 8;
            uint32_t a[4][4], b[4][2];
            #pragma unroll
            for (int i = 0; i < 4; ++i) {
                a[i][0] = cvt_u(Asb[(wm0 + 16*i + g    ) * 36 + kb + q    ]);
                a[i][1] = cvt_u(Asb[(wm0 + 16*i + g + 8) * 36 + kb + q    ]);
                a[i][2] = cvt_u(Asb[(wm0 + 16*i + g    ) * 36 + kb + q + 4]);
                a[i][3] = cvt_u(Asb[(wm0 + 16*i + g + 8) * 36 + kb + q + 4]);
            }
            #pragma unroll
            for (int j = 0; j < 4; ++j) {
                b[j][0] = cvt_u(Bsb[(wn0 + 8*j + g) * 36 + kb + q    ]);
                b[j][1] = cvt_u(Bsb[(wn0 + 8*j + g) * 36 + kb + q + 4]);
            }
            #pragma unroll
            for (int i = 0; i < 4; ++i)
                #pragma unroll
                for (int j = 0; j < 4; ++j)
                    MMA_TF32(acc[i][j], a[i], b[j]);
        }
        __syncthreads();
    }

    #pragma unroll
    for (int i = 0; i < 4; ++i) {
        #pragma unroll
        for (int rr = 0; rr < 2; ++rr) {
            const int gr = row0 + wm0 + 16*i + g + rr*8;
            #pragma unroll
            for (int j = 0; j < 4; ++j) {
                const int gc = col0 + wn0 + 8*j + 2*q;
                const float v0 = acc[i][j][rr*2 + 0];
                const float v1 = acc[i][j][rr*2 + 1];
                float2 bv = *(const float2*)&bias[gc];
                if (MODE == 0) {
                    const int b = gr >> 11, s = gr & 2047;
                    const int h = gc >> 6, d = gc & 63;
                    *(float2*)&C[(((size_t)(b*HH + h))*SS + s)*DH + d] =
                        make_float2(v0 + bv.x, v1 + bv.y);
                } else {
                    *(float2*)&C[(size_t)gr * DD + gc] =
                        make_float2(v0 + bv.x, v1 + bv.y);
                }
            }
        }
    }
}

// ---------------------------------------------------------------------------
// Scores: per z: S = Q@K^T * 0.125, masked -> raw into weights region.
// Single BK=64 slab (K=DH). Fragments staged to smem; epilogue is
// warp-per-row: lane l owns float4 at col 4l -> fully coalesced LDS/LDG/STG,
// butterfly row reductions for (max, expsum) partials into g_Part.
// ---------------------------------------------------------------------------
__global__ __launch_bounds__(256, 2)
void scores_kernel(const float* __restrict__ Q, const float* __restrict__ Kh,
                   const int* __restrict__ maskAll, float* __restrict__ Wraw,
                   float2* __restrict__ Part)
{
    extern __shared__ float sm[];
    float* As = sm;            // 128 x 68
    float* Bs = sm + 8704;     // 128 x 68
    float* sW = sm;            // reused after MMA: 128 x 132

    const int tid = threadIdx.x;
    const int wid = tid >> 5, lane = tid & 31;
    const int g = lane >> 2, q = lane & 3;
    const int wm0 = (wid >> 2) * 64;
    const int wn0 = (wid & 3) * 32;
    const int z = blockIdx.z;
    const int row0 = blockIdx.y * 128;
    const int col0 = blockIdx.x * 128;

    const float* Qz = Q  + (size_t)z * SS * DH;
    const float* Kz = Kh + (size_t)z * SS * DH;
    float* Cz = Wraw + (size_t)z * SS * SS;
    const int* mask = maskAll + (size_t)(z / HH) * SS * SS;

    #pragma unroll
    for (int it = 0; it < 8; ++it) {
        const int idx = tid + it * 256;
        const int r = idx >> 4, c4 = (idx & 15) << 2;
        float4 va = *(const float4*)&Qz[(size_t)(row0 + r) * DH + c4];
        *(float4*)&As[r * 68 + c4] = make_float4(to_tf32(va.x), to_tf32(va.y),
                                                 to_tf32(va.z), to_tf32(va.w));
        float4 vb = *(const float4*)&Kz[(size_t)(col0 + r) * DH + c4];
        *(float4*)&Bs[r * 68 + c4] = make_float4(to_tf32(vb.x), to_tf32(vb.y),
                                                 to_tf32(vb.z), to_tf32(vb.w));
    }
    __syncthreads();

    float acc[4][4][4];
    #pragma unroll
    for (int i = 0; i < 4; ++i)
        #pragma unroll
        for (int j = 0; j < 4; ++j)
            #pragma unroll
            for (int r = 0; r < 4; ++r) acc[i][j][r] = 0.0f;

    #pragma unroll
    for (int kk = 0; kk < 8; ++kk) {
        const int kb = kk * 8;
        uint32_t a[4][4], b[4][2];
        #pragma unroll
        for (int i = 0; i < 4; ++i) {
            a[i][0] = __float_as_uint(As[(wm0 + 16*i + g    ) * 68 + kb + q    ]);
            a[i][1] = __float_as_uint(As[(wm0 + 16*i + g + 8) * 68 + kb + q    ]);
            a[i][2] = __float_as_uint(As[(wm0 + 16*i + g    ) * 68 + kb + q + 4]);
            a[i][3] = __float_as_uint(As[(wm0 + 16*i + g + 8) * 68 + kb + q + 4]);
        }
        #pragma unroll
        for (int j = 0; j < 4; ++j) {
            b[j][0] = __float_as_uint(Bs[(wn0 + 8*j + g) * 68 + kb + q    ]);
            b[j][1] = __float_as_uint(Bs[(wn0 + 8*j + g) * 68 + kb + q + 4]);
        }
        #pragma unroll
        for (int i = 0; i < 4; ++i)
            #pragma unroll
            for (int j = 0; j < 4; ++j)
                MMA_TF32(acc[i][j], a[i], b[j]);
    }
    __syncthreads();   // all warps done reading As/Bs -> safe to reuse as sW

    // fragments -> smem tile (scaled)
    #pragma unroll
    for (int i = 0; i < 4; ++i) {
        #pragma unroll
        for (int rr = 0; rr < 2; ++rr) {
            const int R = wm0 + 16*i + g + rr*8;
            #pragma unroll
            for (int j = 0; j < 4; ++j) {
                const int c = wn0 + 8*j + 2*q;
                *(float2*)&sW[R * 132 + c] =
                    make_float2(acc[i][j][rr*2] * 0.125f, acc[i][j][rr*2+1] * 0.125f);
            }
        }
    }
    __syncthreads();

    // Warp-per-row epilogue: warp wid sweeps rows wid*16..wid*16+15.
    // Lane l owns cols [4l, 4l+4): coalesced 512B LDS/LDG/STG per row.
    {
        const int c4 = lane << 2;
        #pragma unroll
        for (int rr = 0; rr < 16; ++rr) {
            const int r  = wid * 16 + rr;
            const int gr = row0 + r;
            float4 v = *(const float4*)&sW[r * 132 + c4];
            int4  mv = *(const int4*)&mask[(size_t)gr * SS + col0 + c4];
            v.x = mv.x ? v.x : -INFINITY;
            v.y = mv.y ? v.y : -INFINITY;
            v.z = mv.z ? v.z : -INFINITY;
            v.w = mv.w ? v.w : -INFINITY;
            *(float4*)&Cz[(size_t)gr * SS + col0 + c4] = v;

            // row max (butterfly)
            float m = fmaxf(fmaxf(v.x, v.y), fmaxf(v.z, v.w));
            #pragma unroll
            for (int o = 16; o; o >>= 1)
                m = fmaxf(m, __shfl_xor_sync(0xffffffffu, m, o));
            // row expsum (butterfly); per-lane guard handles all-masked rows
            float s = 0.0f;
            s += (v.x > -INFINITY) ? __expf(v.x - m) : 0.0f;
            s += (v.y > -INFINITY) ? __expf(v.y - m) : 0.0f;
            s += (v.z > -INFINITY) ? __expf(v.z - m) : 0.0f;
            s += (v.w > -INFINITY) ? __expf(v.w - m) : 0.0f;
            #pragma unroll
            for (int o = 16; o; o >>= 1)
                s += __shfl_xor_sync(0xffffffffu, s, o);
            if (lane == 0)
                Part[((size_t)z * SS + gr) * 16 + blockIdx.x] = make_float2(m, s);
        }
    }
}

// ---------------------------------------------------------------------------
// Reduce partials -> per-row (max, 1/sum)
// ---------------------------------------------------------------------------
__global__ __launch_bounds__(256)
void reduce_stats(const float2* __restrict__ Part, float2* __restrict__ Stats)
{
    const int row = blockIdx.x * 256 + threadIdx.x;
    float2 p[16];
    #pragma unroll
    for (int i = 0; i < 16; ++i) p[i] = Part[(size_t)row * 16 + i];
    float M = -INFINITY;
    #pragma unroll
    for (int i = 0; i < 16; ++i) M = fmaxf(M, p[i].x);
    float S = 0.0f;
    #pragma unroll
    for (int i = 0; i < 16; ++i)
        S += (p[i].x > -INFINITY) ? p[i].y * __expf(p[i].x - M) : 0.0f;
    Stats[row] = make_float2(M, (S > 0.0f) ? 1.0f / S : 0.0f);
}

// ---------------------------------------------------------------------------
// AV fused with softmax-apply: reads raw scores, computes w=exp(x-M)*invS,
// writes normalized weights IN PLACE (final output; per-thread RMW of its
// own addresses -> race-free), and accumulates W@V.
// BM=128, BK=32, reg-staged double buffer, warp tile 32x32.
// ---------------------------------------------------------------------------
__global__ __launch_bounds__(256, 2)
void mma_av(float* __restrict__ Wts, const float* __restrict__ Vh,
            const float2* __restrict__ Stats, float* __restrict__ Ctx)
{
    __shared__ float As[2][128][36];
    __shared__ float Bs[2][32][68];
    __shared__ float sM[128], sI[128];

    const int z = blockIdx.y;
    float* Aw = Wts + (size_t)z * SS * SS;
    const float* Vv = Vh + (size_t)z * SS * DH;
    const int row0 = blockIdx.x * 128;

    const int tid = threadIdx.x;
    const int wid = tid >> 5, lane = tid & 31;
    const int g = lane >> 2, q = lane & 3;
    const int wm0 = (wid >> 1) * 32;
    const int wn0 = (wid & 1) * 32;

    if (tid < 128) {
        float2 st = Stats[(size_t)z * SS + row0 + tid];
        sM[tid] = st.x; sI[tid] = st.y;
    }

    float acc[2][4][4];
    #pragma unroll
    for (int i = 0; i < 2; ++i)
        #pragma unroll
        for (int j = 0; j < 4; ++j)
            #pragma unroll
            for (int r = 0; r < 4; ++r) acc[i][j][r] = 0.0f;

    float4 ra[4], rb[2];
    #pragma unroll
    for (int it = 0; it < 4; ++it) {
        const int idx = tid + it * 256;
        const int r = idx >> 3, c4 = (idx & 7) << 2;
        ra[it] = *(const float4*)&Aw[(size_t)(row0 + r) * SS + c4];
    }
    #pragma unroll
    for (int it = 0; it < 2; ++it) {
        const int idx = tid + it * 256;
        const int r = idx >> 4, c4 = (idx & 15) << 2;
        rb[it] = *(const float4*)&Vv[(size_t)r * DH + c4];
    }
    __syncthreads();   // stats visible

    for (int t = 0; t < SS / 32; ++t) {
        const int kt = t * 32;
        const int st = t & 1;
        #pragma unroll
        for (int it = 0; it < 4; ++it) {
            const int idx = tid + it * 256;
            const int r = idx >> 3, c4 = (idx & 7) << 2;
            const float M = sM[r], I = sI[r];
            float4 w;
            w.x = __expf(ra[it].x - M) * I;
            w.y = __expf(ra[it].y - M) * I;
            w.z = __expf(ra[it].z - M) * I;
            w.w = __expf(ra[it].w - M) * I;
            *(float4*)&Aw[(size_t)(row0 + r) * SS + kt + c4] = w;   // final weights
            *(float4*)&As[st][r][c4] = make_float4(to_tf32(w.x), to_tf32(w.y),
                                                   to_tf32(w.z), to_tf32(w.w));
        }
        #pragma unroll
        for (int it = 0; it < 2; ++it) {
            const int idx = tid + it * 256;
            const int r = idx >> 4, c4 = (idx & 15) << 2;
            *(float4*)&Bs[st][r][c4] = make_float4(to_tf32(rb[it].x), to_tf32(rb[it].y),
                                                   to_tf32(rb[it].z), to_tf32(rb[it].w));
        }
        __syncthreads();
        if (t + 1 < SS / 32) {
            const int kt2 = kt + 32;
            #pragma unroll
            for (int it = 0; it < 4; ++it) {
                const int idx = tid + it * 256;
                const int r = idx >> 3, c4 = (idx & 7) << 2;
                ra[it] = *(const float4*)&Aw[(size_t)(row0 + r) * SS + kt2 + c4];
            }
            #pragma unroll
            for (int it = 0; it < 2; ++it) {
                const int idx = tid + it * 256;
                const int r = idx >> 4, c4 = (idx & 15) << 2;
                rb[it] = *(const float4*)&Vv[(size_t)(kt2 + r) * DH + c4];
            }
        }
        #pragma unroll
        for (int kk = 0; kk < 4; ++kk) {
            const int kb = kk * 8;
            uint32_t a[2][4], b[4][2];
            #pragma unroll
            for (int i = 0; i < 2; ++i) {
                a[i][0] = __float_as_uint(As[st][wm0 + 16*i + g    ][kb + q    ]);
                a[i][1] = __float_as_uint(As[st][wm0 + 16*i + g + 8][kb + q    ]);
                a[i][2] = __float_as_uint(As[st][wm0 + 16*i + g    ][kb + q + 4]);
                a[i][3] = __float_as_uint(As[st][wm0 + 16*i + g + 8][kb + q + 4]);
            }
            #pragma unroll
            for (int j = 0; j < 4; ++j) {
                b[j][0] = __float_as_uint(Bs[st][kb + q    ][wn0 + 8*j + g]);
                b[j][1] = __float_as_uint(Bs[st][kb + q + 4][wn0 + 8*j + g]);
            }
            #pragma unroll
            for (int i = 0; i < 2; ++i)
                #pragma unroll
                for (int j = 0; j < 4; ++j)
                    MMA_TF32(acc[i][j], a[i], b[j]);
        }
    }

    const int b = z / HH, h = z % HH;
    #pragma unroll
    for (int i = 0; i < 2; ++i) {
        #pragma unroll
        for (int rr = 0; rr < 2; ++rr) {
            const int s = row0 + wm0 + 16*i + g + rr*8;
            #pragma unroll
            for (int j = 0; j < 4; ++j) {
                const int n = wn0 + 8*j + 2*q;
                *(float2*)&Ctx[((size_t)(b*SS + s))*DD + h*64 + n] =
                    make_float2(acc[i][j][rr*2], acc[i][j][rr*2 + 1]);
            }
        }
    }
}

// ---------------------------------------------------------------------------
extern "C" void kernel_launch(void* const* d_in, const int* in_sizes, int n_in,
                              void* d_out, int out_size)
{
    const float* q       = (const float*)d_in[0];
    const float* k       = (const float*)d_in[1];
    const float* v       = (const float*)d_in[2];
    const int*   mask    = (const int*)d_in[3];
    const float* wq_w    = (const float*)d_in[4];
    const float* wq_b    = (const float*)d_in[5];
    const float* wk_w    = (const float*)d_in[6];
    const float* wk_b    = (const float*)d_in[7];
    const float* wv_w    = (const float*)d_in[8];
    const float* wv_b    = (const float*)d_in[9];
    const float* dense_w = (const float*)d_in[10];
    const float* dense_b = (const float*)d_in[11];

    float* out = (float*)d_out;
    float* wts = out + (size_t)BB * SS * DD;

    void *pQ, *pK, *pV, *pC, *pP, *pS;
    cudaGetSymbolAddress(&pQ, g_Q);
    cudaGetSymbolAddress(&pK, g_K);
    cudaGetSymbolAddress(&pV, g_V);
    cudaGetSymbolAddress(&pC, g_Ctx);
    cudaGetSymbolAddress(&pP, g_Part);
    cudaGetSymbolAddress(&pS, g_Stats);
    float*  gQ = (float*)pQ;
    float*  gK = (float*)pK;
    float*  gV = (float*)pV;
    float*  gC = (float*)pC;
    float2* gP = (float2*)pP;
    float2* gS = (float2*)pS;

    const int SM_GEMM = 73728;
    const int SM_SC   = 73728;
    static int inited = 0;
    if (!inited) {
        cudaFuncSetAttribute(mma_nt<0>, cudaFuncAttributeMaxDynamicSharedMemorySize, SM_GEMM);
        cudaFuncSetAttribute(mma_nt<1>, cudaFuncAttributeMaxDynamicSharedMemorySize, SM_GEMM);
        cudaFuncSetAttribute(scores_kernel, cudaFuncAttributeMaxDynamicSharedMemorySize, SM_SC);
        inited = 1;
    }

    const dim3 blk(256);
    const dim3 gproj(DD / 128, MROWS / 128, 1);       // (8, 32)

    mma_nt<0><<<gproj, blk, SM_GEMM>>>(q, wq_w, wq_b, gQ);
    mma_nt<0><<<gproj, blk, SM_GEMM>>>(k, wk_w, wk_b, gK);
    mma_nt<0><<<gproj, blk, SM_GEMM>>>(v, wv_w, wv_b, gV);

    const dim3 gsc(SS / 128, SS / 128, BH);           // (16, 16, 32)
    scores_kernel<<<gsc, blk, SM_SC>>>(gQ, gK, mask, wts, gP);

    reduce_stats<<<NROWTOT / 256, 256>>>(gP, gS);

    const dim3 gav(SS / 128, BH, 1);                  // (16, 32)
    mma_av<<<gav, blk>>>(wts, gV, gS, gC);

    mma_nt<1><<<gproj, blk, SM_GEMM>>>(gC, dense_w, dense_b, out);
}

// round 9
// speedup vs baseline: 1.2903x; 1.0606x over previous
#include <cuda_runtime.h>
#include <cuda_bf16.h>
#include <math.h>
#include <stdint.h>

#define BB 2
#define SS 2048
#define DD 1024
#define HH 16
#define DH 64
#define BH (BB*HH)          // 32
#define MROWS (BB*SS)       // 4096
#define NROWTOT (BH*SS)     // 65536 score rows
#define NWORDS (BB*SS*(SS/32))   // mask bit-words

// Scratch (device globals: allocation-free)
__device__ float    g_Q[BH * SS * DH];
__device__ float    g_K[BH * SS * DH];
__device__ float    g_V[BH * SS * DH];
__device__ float    g_Ctx[MROWS * DD];
__device__ float2   g_Part[(size_t)NROWTOT * 4];  // per-row per-colgroup (max, expsum)
__device__ float2   g_Stats[NROWTOT];             // per-row (max, 1/sum)
__device__ uint32_t g_MaskBits[NWORDS];           // 1 bit per mask entry

__device__ __forceinline__ float to_tf32(float x) {
    uint32_t u;
    asm("cvt.rna.tf32.f32 %0, %1;" : "=r"(u) : "f"(x));
    return __uint_as_float(u);
}
__device__ __forceinline__ uint32_t cvt_u(float x) {
    uint32_t u;
    asm("cvt.rna.tf32.f32 %0, %1;" : "=r"(u) : "f"(x));
    return u;
}

#define MMA_TF32(c, a, b)                                                     \
    asm volatile(                                                             \
        "mma.sync.aligned.m16n8k8.row.col.f32.tf32.tf32.f32 "                 \
        "{%0,%1,%2,%3},{%4,%5,%6,%7},{%8,%9},{%0,%1,%2,%3};\n"                \
        : "+f"(c[0]), "+f"(c[1]), "+f"(c[2]), "+f"(c[3])                      \
        : "r"(a[0]), "r"(a[1]), "r"(a[2]), "r"(a[3]), "r"(b[0]), "r"(b[1]))

#define CP16(dst_u32, src_ptr)                                                \
    asm volatile("cp.async.ca.shared.global [%0], [%1], 16;\n"                \
                 :: "r"(dst_u32), "l"(src_ptr))

__device__ __forceinline__ void sm_merge(float& m, float& s, float om, float os) {
    float M = fmaxf(m, om);
    float e1 = (m  > -INFINITY) ? __expf(m  - M) : 0.0f;
    float e2 = (om > -INFINITY) ? __expf(om - M) : 0.0f;
    s = s * e1 + os * e2;
    m = M;
}

// ---------------------------------------------------------------------------
// Mask int32 -> bitmask. One thread per 32-entry word.
// ---------------------------------------------------------------------------
__global__ __launch_bounds__(256)
void maskbits_kernel(const int* __restrict__ mask, uint32_t* __restrict__ bits)
{
    const int w = blockIdx.x * 256 + threadIdx.x;
    const int* p = mask + (size_t)w * 32;
    uint32_t m = 0;
    #pragma unroll
    for (int c = 0; c < 8; ++c) {
        int4 v = *(const int4*)&p[c * 4];
        m |= (uint32_t)(v.x != 0) << (c*4    );
        m |= (uint32_t)(v.y != 0) << (c*4 + 1);
        m |= (uint32_t)(v.z != 0) << (c*4 + 2);
        m |= (uint32_t)(v.w != 0) << (c*4 + 3);
    }
    bits[w] = m;
}

// ---------------------------------------------------------------------------
// TF32 MMA GEMM with cp.async 2-stage pipeline: C = A*B^T + bias.
// A[M,1024] rm, B[N,1024] rm. BM=BN=128, BK=32, 256 thr, warp tile 64x32.
// MODE 0: proj (scatter to [B,H,S,DH]) | MODE 1: dense (row-major)
// ---------------------------------------------------------------------------
template<int MODE>
__global__ __launch_bounds__(256, 2)
void mma_nt(const float* __restrict__ A, const float* __restrict__ Bw,
            const float* __restrict__ bias, float* __restrict__ C)
{
    extern __shared__ float sm[];
    float* pA = sm;               // 2 stages x 128x36
    float* pB = sm + 2 * 4608;

    const int tid = threadIdx.x;
    const int wid = tid >> 5, lane = tid & 31;
    const int g = lane >> 2, q = lane & 3;
    const int wm0 = (wid >> 2) * 64;
    const int wn0 = (wid & 3) * 32;
    const int row0 = blockIdx.y * 128;
    const int col0 = blockIdx.x * 128;
    const int K = DD;

    uint32_t sA = (uint32_t)__cvta_generic_to_shared(pA);
    uint32_t sB = (uint32_t)__cvta_generic_to_shared(pB);

    float acc[4][4][4];
    #pragma unroll
    for (int i = 0; i < 4; ++i)
        #pragma unroll
        for (int j = 0; j < 4; ++j)
            #pragma unroll
            for (int r = 0; r < 4; ++r) acc[i][j][r] = 0.0f;

    auto copy_tile = [&](int st, int kt) {
        #pragma unroll
        for (int it = 0; it < 4; ++it) {
            const int idx = tid + it * 256;
            const int r = idx >> 3, c4 = (idx & 7) << 2;
            CP16(sA + (uint32_t)(st * 4608 + r * 36 + c4) * 4,
                 &A[(size_t)(row0 + r) * K + kt + c4]);
            CP16(sB + (uint32_t)(st * 4608 + r * 36 + c4) * 4,
                 &Bw[(size_t)(col0 + r) * K + kt + c4]);
        }
        asm volatile("cp.async.commit_group;\n");
    };

    copy_tile(0, 0);
    const int T = K / 32;
    for (int t = 0; t < T; ++t) {
        if (t + 1 < T) {
            copy_tile((t + 1) & 1, (t + 1) * 32);
            asm volatile("cp.async.wait_group 1;\n");
        } else {
            asm volatile("cp.async.wait_group 0;\n");
        }
        __syncthreads();
        const float* Asb = pA + (t & 1) * 4608;
        const float* Bsb = pB + (t & 1) * 4608;
        #pragma unroll
        for (int kk = 0; kk < 4; ++kk) {
            const int kb = kk * 8;
            uint32_t a[4][4], b[4][2];
            #pragma unroll
            for (int i = 0; i < 4; ++i) {
                a[i][0] = cvt_u(Asb[(wm0 + 16*i + g    ) * 36 + kb + q    ]);
                a[i][1] = cvt_u(Asb[(wm0 + 16*i + g + 8) * 36 + kb + q    ]);
                a[i][2] = cvt_u(Asb[(wm0 + 16*i + g    ) * 36 + kb + q + 4]);
                a[i][3] = cvt_u(Asb[(wm0 + 16*i + g + 8) * 36 + kb + q + 4]);
            }
            #pragma unroll
            for (int j = 0; j < 4; ++j) {
                b[j][0] = cvt_u(Bsb[(wn0 + 8*j + g) * 36 + kb + q    ]);
                b[j][1] = cvt_u(Bsb[(wn0 + 8*j + g) * 36 + kb + q + 4]);
            }
            #pragma unroll
            for (int i = 0; i < 4; ++i)
                #pragma unroll
                for (int j = 0; j < 4; ++j)
                    MMA_TF32(acc[i][j], a[i], b[j]);
        }
        __syncthreads();
    }

    #pragma unroll
    for (int i = 0; i < 4; ++i) {
        #pragma unroll
        for (int rr = 0; rr < 2; ++rr) {
            const int gr = row0 + wm0 + 16*i + g + rr*8;
            #pragma unroll
            for (int j = 0; j < 4; ++j) {
                const int gc = col0 + wn0 + 8*j + 2*q;
                const float v0 = acc[i][j][rr*2 + 0];
                const float v1 = acc[i][j][rr*2 + 1];
                float2 bv = *(const float2*)&bias[gc];
                if (MODE == 0) {
                    const int b = gr >> 11, s = gr & 2047;
                    const int h = gc >> 6, d = gc & 63;
                    *(float2*)&C[(((size_t)(b*HH + h))*SS + s)*DH + d] =
                        make_float2(v0 + bv.x, v1 + bv.y);
                } else {
                    *(float2*)&C[(size_t)gr * DD + gc] =
                        make_float2(v0 + bv.x, v1 + bv.y);
                }
            }
        }
    }
}

// ---------------------------------------------------------------------------
// Scores v2: per (z, row-block, col-group of 512): Q tile resident, loop 4
// K tiles with cp.async double-buffer. Masked raw scores -> weights region
// (fragment writes), online per-row (max, expsum) across the 4 tiles ->
// g_Part[row][colgroup]. Bitmask for mask tests.
// smem floats: sQ 8704 | sK 2x8704 | red_m 512 | red_s 512  = 27136
// ---------------------------------------------------------------------------
#define SC_SMEM_FLOATS (8704 + 2*8704 + 512 + 512)

__global__ __launch_bounds__(256, 2)
void scores_kernel(const float* __restrict__ Q, const float* __restrict__ Kh,
                   const uint32_t* __restrict__ mbits, float* __restrict__ Wraw,
                   float2* __restrict__ Part)
{
    extern __shared__ float sm[];
    float* sQ = sm;                      // 128 x 68
    float* sK = sm + 8704;               // 2 x 128 x 68
    float* red_m = sm + 8704 + 17408;    // 128 x 4
    float* red_s = red_m + 512;          // 128 x 4

    const int tid = threadIdx.x;
    const int wid = tid >> 5, lane = tid & 31;
    const int g = lane >> 2, q = lane & 3;
    const int wm0 = (wid >> 2) * 64;
    const int wn0 = (wid & 3) * 32;
    const int wc  = wid & 3;
    const int z = blockIdx.z;
    const int row0 = blockIdx.y * 128;
    const int cg0 = blockIdx.x * 512;

    const float* Qz = Q  + (size_t)z * SS * DH;
    const float* Kz = Kh + (size_t)z * SS * DH;
    float* Cz = Wraw + (size_t)z * SS * SS;
    const uint32_t* mrow0 = mbits + (size_t)(z >> 4) * SS * (SS/32);

    uint32_t sQa = (uint32_t)__cvta_generic_to_shared(sQ);
    uint32_t sKa = (uint32_t)__cvta_generic_to_shared(sK);

    // Prologue: Q + K0 (group), K1 (group)
    {
        #pragma unroll
        for (int it = 0; it < 8; ++it) {
            const int idx = tid + it * 256;
            const int r = idx >> 4, c4 = (idx & 15) << 2;
            CP16(sQa + (uint32_t)(r * 68 + c4) * 4,
                 &Qz[(size_t)(row0 + r) * DH + c4]);
            CP16(sKa + (uint32_t)(r * 68 + c4) * 4,
                 &Kz[(size_t)(cg0 + r) * DH + c4]);
        }
        asm volatile("cp.async.commit_group;\n");
        #pragma unroll
        for (int it = 0; it < 8; ++it) {
            const int idx = tid + it * 256;
            const int r = idx >> 4, c4 = (idx & 15) << 2;
            CP16(sKa + (uint32_t)(8704 + r * 68 + c4) * 4,
                 &Kz[(size_t)(cg0 + 128 + r) * DH + c4]);
        }
        asm volatile("cp.async.commit_group;\n");
    }

    float m8[4][2], s8[4][2];
    #pragma unroll
    for (int i = 0; i < 4; ++i)
        #pragma unroll
        for (int rr = 0; rr < 2; ++rr) { m8[i][rr] = -INFINITY; s8[i][rr] = 0.0f; }

    for (int t = 0; t < 4; ++t) {
        if (t < 3) {
            asm volatile("cp.async.wait_group 1;\n");
        } else {
            asm volatile("cp.async.wait_group 0;\n");
        }
        __syncthreads();

        const float* Ksb = sK + (t & 1) * 8704;
        float acc[4][4][4];
        #pragma unroll
        for (int i = 0; i < 4; ++i)
            #pragma unroll
            for (int j = 0; j < 4; ++j)
                #pragma unroll
                for (int r = 0; r < 4; ++r) acc[i][j][r] = 0.0f;

        #pragma unroll
        for (int kk = 0; kk < 8; ++kk) {
            const int kb = kk * 8;
            uint32_t a[4][4], b[4][2];
            #pragma unroll
            for (int i = 0; i < 4; ++i) {
                a[i][0] = cvt_u(sQ[(wm0 + 16*i + g    ) * 68 + kb + q    ]);
                a[i][1] = cvt_u(sQ[(wm0 + 16*i + g + 8) * 68 + kb + q    ]);
                a[i][2] = cvt_u(sQ[(wm0 + 16*i + g    ) * 68 + kb + q + 4]);
                a[i][3] = cvt_u(sQ[(wm0 + 16*i + g + 8) * 68 + kb + q + 4]);
            }
            #pragma unroll
            for (int j = 0; j < 4; ++j) {
                b[j][0] = cvt_u(Ksb[(wn0 + 8*j + g) * 68 + kb + q    ]);
                b[j][1] = cvt_u(Ksb[(wn0 + 8*j + g) * 68 + kb + q + 4]);
            }
            #pragma unroll
            for (int i = 0; i < 4; ++i)
                #pragma unroll
                for (int j = 0; j < 4; ++j)
                    MMA_TF32(acc[i][j], a[i], b[j]);
        }
        __syncthreads();

        // issue load for tile t+2 into the buffer just freed
        if (t + 2 < 4) {
            const int dst = (t & 1) * 8704;
            #pragma unroll
            for (int it = 0; it < 8; ++it) {
                const int idx = tid + it * 256;
                const int r = idx >> 4, c4 = (idx & 15) << 2;
                CP16(sKa + (uint32_t)(dst + r * 68 + c4) * 4,
                     &Kz[(size_t)(cg0 + (t + 2) * 128 + r) * DH + c4]);
            }
            asm volatile("cp.async.commit_group;\n");
        }

        // Epilogue (overlaps in-flight load): bitmask + write + online stats
        const int colb = cg0 + t * 128 + wn0;      // warp's 32-col span base
        const int wword = colb >> 5;
        #pragma unroll
        for (int i = 0; i < 4; ++i) {
            #pragma unroll
            for (int rr = 0; rr < 2; ++rr) {
                const int gr = row0 + wm0 + 16*i + g + rr*8;
                const uint32_t mw = mrow0[(size_t)gr * (SS/32) + wword];
                float vals[8];
                float mt = -INFINITY;
                #pragma unroll
                for (int j = 0; j < 4; ++j) {
                    const int cl = 8*j + 2*q;
                    float v0 = (mw >> cl) & 1u ? acc[i][j][rr*2    ] * 0.125f : -INFINITY;
                    float v1 = (mw >> (cl+1)) & 1u ? acc[i][j][rr*2 + 1] * 0.125f : -INFINITY;
                    *(float2*)&Cz[(size_t)gr * SS + colb + cl] = make_float2(v0, v1);
                    vals[j*2] = v0; vals[j*2+1] = v1;
                    mt = fmaxf(mt, fmaxf(v0, v1));
                }
                const float Mn = fmaxf(m8[i][rr], mt);
                if (Mn > -INFINITY) {
                    float add = 0.0f;
                    #pragma unroll
                    for (int e = 0; e < 8; ++e)
                        add += (vals[e] > -INFINITY) ? __expf(vals[e] - Mn) : 0.0f;
                    const float keep = (m8[i][rr] > -INFINITY)
                                     ? s8[i][rr] * __expf(m8[i][rr] - Mn) : 0.0f;
                    s8[i][rr] = keep + add;
                    m8[i][rr] = Mn;
                }
            }
        }
    }

    // reduce stats: across q lanes, then across 4 col-warps
    #pragma unroll
    for (int i = 0; i < 4; ++i) {
        #pragma unroll
        for (int rr = 0; rr < 2; ++rr) {
            float m = m8[i][rr], s = s8[i][rr];
            #pragma unroll
            for (int o = 1; o <= 2; o <<= 1) {
                float om = __shfl_xor_sync(0xffffffffu, m, o);
                float os = __shfl_xor_sync(0xffffffffu, s, o);
                sm_merge(m, s, om, os);
            }
            if (q == 0) {
                const int R = wm0 + 16*i + g + rr*8;
                red_m[R * 4 + wc] = m;
                red_s[R * 4 + wc] = s;
            }
        }
    }
    __syncthreads();
    if (tid < 128) {
        float m = red_m[tid * 4], s = red_s[tid * 4];
        #pragma unroll
        for (int w = 1; w < 4; ++w)
            sm_merge(m, s, red_m[tid * 4 + w], red_s[tid * 4 + w]);
        Part[((size_t)z * SS + row0 + tid) * 4 + blockIdx.x] = make_float2(m, s);
    }
}

// ---------------------------------------------------------------------------
// Reduce partials -> per-row (max, 1/sum)
// ---------------------------------------------------------------------------
__global__ __launch_bounds__(256)
void reduce_stats(const float2* __restrict__ Part, float2* __restrict__ Stats)
{
    const int row = blockIdx.x * 256 + threadIdx.x;
    float2 p[4];
    #pragma unroll
    for (int i = 0; i < 4; ++i) p[i] = Part[(size_t)row * 4 + i];
    float M = -INFINITY;
    #pragma unroll
    for (int i = 0; i < 4; ++i) M = fmaxf(M, p[i].x);
    float S = 0.0f;
    #pragma unroll
    for (int i = 0; i < 4; ++i)
        S += (p[i].x > -INFINITY) ? p[i].y * __expf(p[i].x - M) : 0.0f;
    Stats[row] = make_float2(M, (S > 0.0f) ? 1.0f / S : 0.0f);
}

// ---------------------------------------------------------------------------
// AV fused with softmax-apply: reads raw scores, computes w=exp(x-M)*invS,
// writes normalized weights IN PLACE (final output; per-thread RMW of its
// own addresses -> race-free), and accumulates W@V.
// BM=128, BK=32, reg-staged double buffer, warp tile 32x32.
// ---------------------------------------------------------------------------
__global__ __launch_bounds__(256, 2)
void mma_av(float* __restrict__ Wts, const float* __restrict__ Vh,
            const float2* __restrict__ Stats, float* __restrict__ Ctx)
{
    __shared__ float As[2][128][36];
    __shared__ float Bs[2][32][68];
    __shared__ float sM[128], sI[128];

    const int z = blockIdx.y;
    float* Aw = Wts + (size_t)z * SS * SS;
    const float* Vv = Vh + (size_t)z * SS * DH;
    const int row0 = blockIdx.x * 128;

    const int tid = threadIdx.x;
    const int wid = tid >> 5, lane = tid & 31;
    const int g = lane >> 2, q = lane & 3;
    const int wm0 = (wid >> 1) * 32;
    const int wn0 = (wid & 1) * 32;

    if (tid < 128) {
        float2 st = Stats[(size_t)z * SS + row0 + tid];
        sM[tid] = st.x; sI[tid] = st.y;
    }

    float acc[2][4][4];
    #pragma unroll
    for (int i = 0; i < 2; ++i)
        #pragma unroll
        for (int j = 0; j < 4; ++j)
            #pragma unroll
            for (int r = 0; r < 4; ++r) acc[i][j][r] = 0.0f;

    float4 ra[4], rb[2];
    #pragma unroll
    for (int it = 0; it < 4; ++it) {
        const int idx = tid + it * 256;
        const int r = idx >> 3, c4 = (idx & 7) << 2;
        ra[it] = *(const float4*)&Aw[(size_t)(row0 + r) * SS + c4];
    }
    #pragma unroll
    for (int it = 0; it < 2; ++it) {
        const int idx = tid + it * 256;
        const int r = idx >> 4, c4 = (idx & 15) << 2;
        rb[it] = *(const float4*)&Vv[(size_t)r * DH + c4];
    }
    __syncthreads();   // stats visible

    for (int t = 0; t < SS / 32; ++t) {
        const int kt = t * 32;
        const int st = t & 1;
        #pragma unroll
        for (int it = 0; it < 4; ++it) {
            const int idx = tid + it * 256;
            const int r = idx >> 3, c4 = (idx & 7) << 2;
            const float M = sM[r], I = sI[r];
            float4 w;
            w.x = __expf(ra[it].x - M) * I;
            w.y = __expf(ra[it].y - M) * I;
            w.z = __expf(ra[it].z - M) * I;
            w.w = __expf(ra[it].w - M) * I;
            *(float4*)&Aw[(size_t)(row0 + r) * SS + kt + c4] = w;   // final weights
            *(float4*)&As[st][r][c4] = make_float4(to_tf32(w.x), to_tf32(w.y),
                                                   to_tf32(w.z), to_tf32(w.w));
        }
        #pragma unroll
        for (int it = 0; it < 2; ++it) {
            const int idx = tid + it * 256;
            const int r = idx >> 4, c4 = (idx & 15) << 2;
            *(float4*)&Bs[st][r][c4] = make_float4(to_tf32(rb[it].x), to_tf32(rb[it].y),
                                                   to_tf32(rb[it].z), to_tf32(rb[it].w));
        }
        __syncthreads();
        if (t + 1 < SS / 32) {
            const int kt2 = kt + 32;
            #pragma unroll
            for (int it = 0; it < 4; ++it) {
                const int idx = tid + it * 256;
                const int r = idx >> 3, c4 = (idx & 7) << 2;
                ra[it] = *(const float4*)&Aw[(size_t)(row0 + r) * SS + kt2 + c4];
            }
            #pragma unroll
            for (int it = 0; it < 2; ++it) {
                const int idx = tid + it * 256;
                const int r = idx >> 4, c4 = (idx & 15) << 2;
                rb[it] = *(const float4*)&Vv[(size_t)(kt2 + r) * DH + c4];
            }
        }
        #pragma unroll
        for (int kk = 0; kk < 4; ++kk) {
            const int kb = kk * 8;
            uint32_t a[2][4], b[4][2];
            #pragma unroll
            for (int i = 0; i < 2; ++i) {
                a[i][0] = __float_as_uint(As[st][wm0 + 16*i + g    ][kb + q    ]);
                a[i][1] = __float_as_uint(As[st][wm0 + 16*i + g + 8][kb + q    ]);
                a[i][2] = __float_as_uint(As[st][wm0 + 16*i + g    ][kb + q + 4]);
                a[i][3] = __float_as_uint(As[st][wm0 + 16*i + g + 8][kb + q + 4]);
            }
            #pragma unroll
            for (int j = 0; j < 4; ++j) {
                b[j][0] = __float_as_uint(Bs[st][kb + q    ][wn0 + 8*j + g]);
                b[j][1] = __float_as_uint(Bs[st][kb + q + 4][wn0 + 8*j + g]);
            }
            #pragma unroll
            for (int i = 0; i < 2; ++i)
                #pragma unroll
                for (int j = 0; j < 4; ++j)
                    MMA_TF32(acc[i][j], a[i], b[j]);
        }
    }

    const int b = z / HH, h = z % HH;
    #pragma unroll
    for (int i = 0; i < 2; ++i) {
        #pragma unroll
        for (int rr = 0; rr < 2; ++rr) {
            const int s = row0 + wm0 + 16*i + g + rr*8;
            #pragma unroll
            for (int j = 0; j < 4; ++j) {
                const int n = wn0 + 8*j + 2*q;
                *(float2*)&Ctx[((size_t)(b*SS + s))*DD + h*64 + n] =
                    make_float2(acc[i][j][rr*2], acc[i][j][rr*2 + 1]);
            }
        }
    }
}

// ---------------------------------------------------------------------------
extern "C" void kernel_launch(void* const* d_in, const int* in_sizes, int n_in,
                              void* d_out, int out_size)
{
    const float* q       = (const float*)d_in[0];
    const float* k       = (const float*)d_in[1];
    const float* v       = (const float*)d_in[2];
    const int*   mask    = (const int*)d_in[3];
    const float* wq_w    = (const float*)d_in[4];
    const float* wq_b    = (const float*)d_in[5];
    const float* wk_w    = (const float*)d_in[6];
    const float* wk_b    = (const float*)d_in[7];
    const float* wv_w    = (const float*)d_in[8];
    const float* wv_b    = (const float*)d_in[9];
    const float* dense_w = (const float*)d_in[10];
    const float* dense_b = (const float*)d_in[11];

    float* out = (float*)d_out;
    float* wts = out + (size_t)BB * SS * DD;

    void *pQ, *pK, *pV, *pC, *pP, *pS, *pM;
    cudaGetSymbolAddress(&pQ, g_Q);
    cudaGetSymbolAddress(&pK, g_K);
    cudaGetSymbolAddress(&pV, g_V);
    cudaGetSymbolAddress(&pC, g_Ctx);
    cudaGetSymbolAddress(&pP, g_Part);
    cudaGetSymbolAddress(&pS, g_Stats);
    cudaGetSymbolAddress(&pM, g_MaskBits);
    float*    gQ = (float*)pQ;
    float*    gK = (float*)pK;
    float*    gV = (float*)pV;
    float*    gC = (float*)pC;
    float2*   gP = (float2*)pP;
    float2*   gS = (float2*)pS;
    uint32_t* gM = (uint32_t*)pM;

    const int SM_GEMM = 73728;
    const int SM_SC   = SC_SMEM_FLOATS * 4;   // 108544
    static int inited = 0;
    if (!inited) {
        cudaFuncSetAttribute(mma_nt<0>, cudaFuncAttributeMaxDynamicSharedMemorySize, SM_GEMM);
        cudaFuncSetAttribute(mma_nt<1>, cudaFuncAttributeMaxDynamicSharedMemorySize, SM_GEMM);
        cudaFuncSetAttribute(scores_kernel, cudaFuncAttributeMaxDynamicSharedMemorySize, SM_SC);
        inited = 1;
    }

    const dim3 blk(256);

    // 0) mask -> bitmask
    maskbits_kernel<<<NWORDS / 256, 256>>>(mask, gM);

    // 1) QKV projections
    const dim3 gproj(DD / 128, MROWS / 128, 1);       // (8, 32)
    mma_nt<0><<<gproj, blk, SM_GEMM>>>(q, wq_w, wq_b, gQ);
    mma_nt<0><<<gproj, blk, SM_GEMM>>>(k, wk_w, wk_b, gK);
    mma_nt<0><<<gproj, blk, SM_GEMM>>>(v, wv_w, wv_b, gV);

    // 2) Scores -> raw weights region + 4 partials/row
    const dim3 gsc(SS / 512, SS / 128, BH);           // (4, 16, 32)
    scores_kernel<<<gsc, blk, SM_SC>>>(gQ, gK, gM, wts, gP);

    // 3) Per-row stats
    reduce_stats<<<NROWTOT / 256, 256>>>(gP, gS);

    // 4) AV + in-place normalize
    const dim3 gav(SS / 128, BH, 1);                  // (16, 32)
    mma_av<<<gav, blk>>>(wts, gV, gS, gC);

    // 5) Dense
    mma_nt<1><<<gproj, blk, SM_GEMM>>>(gC, dense_w, dense_b, out);
}

// round 10
// speedup vs baseline: 1.3034x; 1.0102x over previous
#include <cuda_runtime.h>
#include <cuda_bf16.h>
#include <math.h>
#include <stdint.h>

#define BB 2
#define SS 2048
#define DD 1024
#define HH 16
#define DH 64
#define BH (BB*HH)          // 32
#define MROWS (BB*SS)       // 4096
#define NROWTOT (BH*SS)     // 65536 score rows
#define NWORDS (BB*SS*(SS/32))   // mask bit-words

// Scratch (device globals: allocation-free)
__device__ float    g_Q[BH * SS * DH];
__device__ float    g_K[BH * SS * DH];
__device__ float    g_V[BH * SS * DH];
__device__ float    g_Ctx[MROWS * DD];
__device__ float2   g_Part[(size_t)NROWTOT * 4];  // per-row per-colgroup (max, expsum)
__device__ float2   g_Stats[NROWTOT];             // per-row (max, 1/sum)
__device__ uint32_t g_MaskBits[NWORDS];           // 1 bit per mask entry

__device__ __forceinline__ float to_tf32(float x) {
    uint32_t u;
    asm("cvt.rna.tf32.f32 %0, %1;" : "=r"(u) : "f"(x));
    return __uint_as_float(u);
}
__device__ __forceinline__ uint32_t cvt_u(float x) {
    uint32_t u;
    asm("cvt.rna.tf32.f32 %0, %1;" : "=r"(u) : "f"(x));
    return u;
}

#define MMA_TF32(c, a, b)                                                     \
    asm volatile(                                                             \
        "mma.sync.aligned.m16n8k8.row.col.f32.tf32.tf32.f32 "                 \
        "{%0,%1,%2,%3},{%4,%5,%6,%7},{%8,%9},{%0,%1,%2,%3};\n"                \
        : "+f"(c[0]), "+f"(c[1]), "+f"(c[2]), "+f"(c[3])                      \
        : "r"(a[0]), "r"(a[1]), "r"(a[2]), "r"(a[3]), "r"(b[0]), "r"(b[1]))

#define CP16(dst_u32, src_ptr)                                                \
    asm volatile("cp.async.ca.shared.global [%0], [%1], 16;\n"                \
                 :: "r"(dst_u32), "l"(src_ptr))

__device__ __forceinline__ void sm_merge(float& m, float& s, float om, float os) {
    float M = fmaxf(m, om);
    float e1 = (m  > -INFINITY) ? __expf(m  - M) : 0.0f;
    float e2 = (om > -INFINITY) ? __expf(om - M) : 0.0f;
    s = s * e1 + os * e2;
    m = M;
}

struct ProjArgs {
    const float* A[3];
    const float* W[3];
    const float* bias[3];
    float* C[3];
};

// ---------------------------------------------------------------------------
// Mask int32 -> bitmask. One thread per 32-entry word.
// ---------------------------------------------------------------------------
__global__ __launch_bounds__(256)
void maskbits_kernel(const int* __restrict__ mask, uint32_t* __restrict__ bits)
{
    const int w = blockIdx.x * 256 + threadIdx.x;
    const int* p = mask + (size_t)w * 32;
    uint32_t m = 0;
    #pragma unroll
    for (int c = 0; c < 8; ++c) {
        int4 v = *(const int4*)&p[c * 4];
        m |= (uint32_t)(v.x != 0) << (c*4    );
        m |= (uint32_t)(v.y != 0) << (c*4 + 1);
        m |= (uint32_t)(v.z != 0) << (c*4 + 2);
        m |= (uint32_t)(v.w != 0) << (c*4 + 3);
    }
    bits[w] = m;
}

// ---------------------------------------------------------------------------
// TF32 MMA GEMM with cp.async 2-stage pipeline: C = A*B^T + bias.
// BM=BN=128, BK=32, 256 thr, warp tile 64x32.
// MODE 0: proj, z-indexed q/k/v (scatter to [B,H,S,DH]) | MODE 1: dense
// ---------------------------------------------------------------------------
template<int MODE>
__global__ __launch_bounds__(256, 2)
void mma_nt(ProjArgs pa)
{
    extern __shared__ float sm[];
    float* pA = sm;               // 2 stages x 128x36
    float* pB = sm + 2 * 4608;

    const int zi = (MODE == 0) ? blockIdx.z : 0;
    const float* A    = pa.A[zi];
    const float* Bw   = pa.W[zi];
    const float* bias = pa.bias[zi];
    float* C          = pa.C[zi];

    const int tid = threadIdx.x;
    const int wid = tid >> 5, lane = tid & 31;
    const int g = lane >> 2, q = lane & 3;
    const int wm0 = (wid >> 2) * 64;
    const int wn0 = (wid & 3) * 32;
    const int row0 = blockIdx.y * 128;
    const int col0 = blockIdx.x * 128;
    const int K = DD;

    uint32_t sA = (uint32_t)__cvta_generic_to_shared(pA);
    uint32_t sB = (uint32_t)__cvta_generic_to_shared(pB);

    float acc[4][4][4];
    #pragma unroll
    for (int i = 0; i < 4; ++i)
        #pragma unroll
        for (int j = 0; j < 4; ++j)
            #pragma unroll
            for (int r = 0; r < 4; ++r) acc[i][j][r] = 0.0f;

    auto copy_tile = [&](int st, int kt) {
        #pragma unroll
        for (int it = 0; it < 4; ++it) {
            const int idx = tid + it * 256;
            const int r = idx >> 3, c4 = (idx & 7) << 2;
            CP16(sA + (uint32_t)(st * 4608 + r * 36 + c4) * 4,
                 &A[(size_t)(row0 + r) * K + kt + c4]);
            CP16(sB + (uint32_t)(st * 4608 + r * 36 + c4) * 4,
                 &Bw[(size_t)(col0 + r) * K + kt + c4]);
        }
        asm volatile("cp.async.commit_group;\n");
    };

    copy_tile(0, 0);
    const int T = K / 32;
    for (int t = 0; t < T; ++t) {
        if (t + 1 < T) {
            copy_tile((t + 1) & 1, (t + 1) * 32);
            asm volatile("cp.async.wait_group 1;\n");
        } else {
            asm volatile("cp.async.wait_group 0;\n");
        }
        __syncthreads();
        const float* Asb = pA + (t & 1) * 4608;
        const float* Bsb = pB + (t & 1) * 4608;
        #pragma unroll
        for (int kk = 0; kk < 4; ++kk) {
            const int kb = kk * 8;
            uint32_t a[4][4], b[4][2];
            #pragma unroll
            for (int i = 0; i < 4; ++i) {
                a[i][0] = cvt_u(Asb[(wm0 + 16*i + g    ) * 36 + kb + q    ]);
                a[i][1] = cvt_u(Asb[(wm0 + 16*i + g + 8) * 36 + kb + q    ]);
                a[i][2] = cvt_u(Asb[(wm0 + 16*i + g    ) * 36 + kb + q + 4]);
                a[i][3] = cvt_u(Asb[(wm0 + 16*i + g + 8) * 36 + kb + q + 4]);
            }
            #pragma unroll
            for (int j = 0; j < 4; ++j) {
                b[j][0] = cvt_u(Bsb[(wn0 + 8*j + g) * 36 + kb + q    ]);
                b[j][1] = cvt_u(Bsb[(wn0 + 8*j + g) * 36 + kb + q + 4]);
            }
            #pragma unroll
            for (int i = 0; i < 4; ++i)
                #pragma unroll
                for (int j = 0; j < 4; ++j)
                    MMA_TF32(acc[i][j], a[i], b[j]);
        }
        __syncthreads();
    }

    #pragma unroll
    for (int i = 0; i < 4; ++i) {
        #pragma unroll
        for (int rr = 0; rr < 2; ++rr) {
            const int gr = row0 + wm0 + 16*i + g + rr*8;
            #pragma unroll
            for (int j = 0; j < 4; ++j) {
                const int gc = col0 + wn0 + 8*j + 2*q;
                const float v0 = acc[i][j][rr*2 + 0];
                const float v1 = acc[i][j][rr*2 + 1];
                float2 bv = *(const float2*)&bias[gc];
                if (MODE == 0) {
                    const int b = gr >> 11, s = gr & 2047;
                    const int h = gc >> 6, d = gc & 63;
                    *(float2*)&C[(((size_t)(b*HH + h))*SS + s)*DH + d] =
                        make_float2(v0 + bv.x, v1 + bv.y);
                } else {
                    *(float2*)&C[(size_t)gr * DD + gc] =
                        make_float2(v0 + bv.x, v1 + bv.y);
                }
            }
        }
    }
}

// ---------------------------------------------------------------------------
// Scores v2: per (z, row-block, col-group of 512): Q tile resident, loop 4
// K tiles with cp.async double-buffer. Masked raw scores -> weights region
// (fragment writes), online per-row (max, expsum) across the 4 tiles ->
// g_Part[row][colgroup]. Bitmask for mask tests.
// ---------------------------------------------------------------------------
#define SC_SMEM_FLOATS (8704 + 2*8704 + 512 + 512)

__global__ __launch_bounds__(256, 2)
void scores_kernel(const float* __restrict__ Q, const float* __restrict__ Kh,
                   const uint32_t* __restrict__ mbits, float* __restrict__ Wraw,
                   float2* __restrict__ Part)
{
    extern __shared__ float sm[];
    float* sQ = sm;                      // 128 x 68
    float* sK = sm + 8704;               // 2 x 128 x 68
    float* red_m = sm + 8704 + 17408;    // 128 x 4
    float* red_s = red_m + 512;          // 128 x 4

    const int tid = threadIdx.x;
    const int wid = tid >> 5, lane = tid & 31;
    const int g = lane >> 2, q = lane & 3;
    const int wm0 = (wid >> 2) * 64;
    const int wn0 = (wid & 3) * 32;
    const int wc  = wid & 3;
    const int z = blockIdx.z;
    const int row0 = blockIdx.y * 128;
    const int cg0 = blockIdx.x * 512;

    const float* Qz = Q  + (size_t)z * SS * DH;
    const float* Kz = Kh + (size_t)z * SS * DH;
    float* Cz = Wraw + (size_t)z * SS * SS;
    const uint32_t* mrow0 = mbits + (size_t)(z >> 4) * SS * (SS/32);

    uint32_t sQa = (uint32_t)__cvta_generic_to_shared(sQ);
    uint32_t sKa = (uint32_t)__cvta_generic_to_shared(sK);

    // Prologue: Q + K0 (group), K1 (group)
    {
        #pragma unroll
        for (int it = 0; it < 8; ++it) {
            const int idx = tid + it * 256;
            const int r = idx >> 4, c4 = (idx & 15) << 2;
            CP16(sQa + (uint32_t)(r * 68 + c4) * 4,
                 &Qz[(size_t)(row0 + r) * DH + c4]);
            CP16(sKa + (uint32_t)(r * 68 + c4) * 4,
                 &Kz[(size_t)(cg0 + r) * DH + c4]);
        }
        asm volatile("cp.async.commit_group;\n");
        #pragma unroll
        for (int it = 0; it < 8; ++it) {
            const int idx = tid + it * 256;
            const int r = idx >> 4, c4 = (idx & 15) << 2;
            CP16(sKa + (uint32_t)(8704 + r * 68 + c4) * 4,
                 &Kz[(size_t)(cg0 + 128 + r) * DH + c4]);
        }
        asm volatile("cp.async.commit_group;\n");
    }

    float m8[4][2], s8[4][2];
    #pragma unroll
    for (int i = 0; i < 4; ++i)
        #pragma unroll
        for (int rr = 0; rr < 2; ++rr) { m8[i][rr] = -INFINITY; s8[i][rr] = 0.0f; }

    for (int t = 0; t < 4; ++t) {
        if (t < 3) {
            asm volatile("cp.async.wait_group 1;\n");
        } else {
            asm volatile("cp.async.wait_group 0;\n");
        }
        __syncthreads();

        const float* Ksb = sK + (t & 1) * 8704;
        float acc[4][4][4];
        #pragma unroll
        for (int i = 0; i < 4; ++i)
            #pragma unroll
            for (int j = 0; j < 4; ++j)
                #pragma unroll
                for (int r = 0; r < 4; ++r) acc[i][j][r] = 0.0f;

        #pragma unroll
        for (int kk = 0; kk < 8; ++kk) {
            const int kb = kk * 8;
            uint32_t a[4][4], b[4][2];
            #pragma unroll
            for (int i = 0; i < 4; ++i) {
                a[i][0] = cvt_u(sQ[(wm0 + 16*i + g    ) * 68 + kb + q    ]);
                a[i][1] = cvt_u(sQ[(wm0 + 16*i + g + 8) * 68 + kb + q    ]);
                a[i][2] = cvt_u(sQ[(wm0 + 16*i + g    ) * 68 + kb + q + 4]);
                a[i][3] = cvt_u(sQ[(wm0 + 16*i + g + 8) * 68 + kb + q + 4]);
            }
            #pragma unroll
            for (int j = 0; j < 4; ++j) {
                b[j][0] = cvt_u(Ksb[(wn0 + 8*j + g) * 68 + kb + q    ]);
                b[j][1] = cvt_u(Ksb[(wn0 + 8*j + g) * 68 + kb + q + 4]);
            }
            #pragma unroll
            for (int i = 0; i < 4; ++i)
                #pragma unroll
                for (int j = 0; j < 4; ++j)
                    MMA_TF32(acc[i][j], a[i], b[j]);
        }
        __syncthreads();

        // issue load for tile t+2 into the buffer just freed
        if (t + 2 < 4) {
            const int dst = (t & 1) * 8704;
            #pragma unroll
            for (int it = 0; it < 8; ++it) {
                const int idx = tid + it * 256;
                const int r = idx >> 4, c4 = (idx & 15) << 2;
                CP16(sKa + (uint32_t)(dst + r * 68 + c4) * 4,
                     &Kz[(size_t)(cg0 + (t + 2) * 128 + r) * DH + c4]);
            }
            asm volatile("cp.async.commit_group;\n");
        }

        // Epilogue (overlaps in-flight load): bitmask + write + online stats
        const int colb = cg0 + t * 128 + wn0;      // warp's 32-col span base
        const int wword = colb >> 5;
        #pragma unroll
        for (int i = 0; i < 4; ++i) {
            #pragma unroll
            for (int rr = 0; rr < 2; ++rr) {
                const int gr = row0 + wm0 + 16*i + g + rr*8;
                const uint32_t mw = mrow0[(size_t)gr * (SS/32) + wword];
                float vals[8];
                float mt = -INFINITY;
                #pragma unroll
                for (int j = 0; j < 4; ++j) {
                    const int cl = 8*j + 2*q;
                    float v0 = (mw >> cl) & 1u ? acc[i][j][rr*2    ] * 0.125f : -INFINITY;
                    float v1 = (mw >> (cl+1)) & 1u ? acc[i][j][rr*2 + 1] * 0.125f : -INFINITY;
                    *(float2*)&Cz[(size_t)gr * SS + colb + cl] = make_float2(v0, v1);
                    vals[j*2] = v0; vals[j*2+1] = v1;
                    mt = fmaxf(mt, fmaxf(v0, v1));
                }
                const float Mn = fmaxf(m8[i][rr], mt);
                if (Mn > -INFINITY) {
                    float add = 0.0f;
                    #pragma unroll
                    for (int e = 0; e < 8; ++e)
                        add += (vals[e] > -INFINITY) ? __expf(vals[e] - Mn) : 0.0f;
                    const float keep = (m8[i][rr] > -INFINITY)
                                     ? s8[i][rr] * __expf(m8[i][rr] - Mn) : 0.0f;
                    s8[i][rr] = keep + add;
                    m8[i][rr] = Mn;
                }
            }
        }
    }

    // reduce stats: across q lanes, then across 4 col-warps
    #pragma unroll
    for (int i = 0; i < 4; ++i) {
        #pragma unroll
        for (int rr = 0; rr < 2; ++rr) {
            float m = m8[i][rr], s = s8[i][rr];
            #pragma unroll
            for (int o = 1; o <= 2; o <<= 1) {
                float om = __shfl_xor_sync(0xffffffffu, m, o);
                float os = __shfl_xor_sync(0xffffffffu, s, o);
                sm_merge(m, s, om, os);
            }
            if (q == 0) {
                const int R = wm0 + 16*i + g + rr*8;
                red_m[R * 4 + wc] = m;
                red_s[R * 4 + wc] = s;
            }
        }
    }
    __syncthreads();
    if (tid < 128) {
        float m = red_m[tid * 4], s = red_s[tid * 4];
        #pragma unroll
        for (int w = 1; w < 4; ++w)
            sm_merge(m, s, red_m[tid * 4 + w], red_s[tid * 4 + w]);
        Part[((size_t)z * SS + row0 + tid) * 4 + blockIdx.x] = make_float2(m, s);
    }
}

// ---------------------------------------------------------------------------
// Reduce partials -> per-row (max, 1/sum)
// ---------------------------------------------------------------------------
__global__ __launch_bounds__(256)
void reduce_stats(const float2* __restrict__ Part, float2* __restrict__ Stats)
{
    const int row = blockIdx.x * 256 + threadIdx.x;
    float2 p[4];
    #pragma unroll
    for (int i = 0; i < 4; ++i) p[i] = Part[(size_t)row * 4 + i];
    float M = -INFINITY;
    #pragma unroll
    for (int i = 0; i < 4; ++i) M = fmaxf(M, p[i].x);
    float S = 0.0f;
    #pragma unroll
    for (int i = 0; i < 4; ++i)
        S += (p[i].x > -INFINITY) ? p[i].y * __expf(p[i].x - M) : 0.0f;
    Stats[row] = make_float2(M, (S > 0.0f) ? 1.0f / S : 0.0f);
}

// ---------------------------------------------------------------------------
// AV fused with softmax-apply, v2: 512 threads, KT=64 per iter (32 iters,
// 1 sync/iter). Reads raw scores, w=exp(x-M)*invS, writes weights in place
// (per-thread RMW of its own addresses -> race-free), accumulates W@V.
// Warp tile 32x16 (4x4 warp grid). Dynamic smem:
//   As 2x128x68 | Bs 2x64x68 | sM 128 | sI 128  = 26368 floats = 105472 B
// ---------------------------------------------------------------------------
#define AV_SMEM_FLOATS (2*8704 + 2*4352 + 256)

__global__ __launch_bounds__(512, 1)
void mma_av(float* __restrict__ Wts, const float* __restrict__ Vh,
            const float2* __restrict__ Stats, float* __restrict__ Ctx)
{
    extern __shared__ float sm[];
    float* As = sm;                    // [2][128][68]
    float* Bs = sm + 2 * 8704;         // [2][64][68]
    float* sM = sm + 2 * 8704 + 2 * 4352;
    float* sI = sM + 128;

    const int z = blockIdx.y;
    float* Aw = Wts + (size_t)z * SS * SS;
    const float* Vv = Vh + (size_t)z * SS * DH;
    const int row0 = blockIdx.x * 128;

    const int tid = threadIdx.x;
    const int wid = tid >> 5, lane = tid & 31;
    const int g = lane >> 2, q = lane & 3;
    const int wm0 = (wid >> 2) * 32;   // 4 row groups
    const int wn0 = (wid & 3) * 16;    // 4 col groups

    if (tid < 128) {
        float2 st = Stats[(size_t)z * SS + row0 + tid];
        sM[tid] = st.x; sI[tid] = st.y;
    }

    float acc[2][2][4];
    #pragma unroll
    for (int i = 0; i < 2; ++i)
        #pragma unroll
        for (int j = 0; j < 2; ++j)
            #pragma unroll
            for (int r = 0; r < 4; ++r) acc[i][j][r] = 0.0f;

    // prologue loads (tile 0): A 128x64, V 64x64
    float4 ra[4], rb[2];
    #pragma unroll
    for (int it = 0; it < 4; ++it) {
        const int idx = tid + it * 512;
        const int r = idx >> 4, c4 = (idx & 15) << 2;
        ra[it] = *(const float4*)&Aw[(size_t)(row0 + r) * SS + c4];
    }
    #pragma unroll
    for (int it = 0; it < 2; ++it) {
        const int idx = tid + it * 512;
        const int r = idx >> 4, c4 = (idx & 15) << 2;
        rb[it] = *(const float4*)&Vv[(size_t)r * DH + c4];
    }
    __syncthreads();   // stats visible

    for (int t = 0; t < SS / 64; ++t) {
        const int kt = t * 64;
        const int st = t & 1;
        // transform + stage tile t; write normalized weights to gmem
        #pragma unroll
        for (int it = 0; it < 4; ++it) {
            const int idx = tid + it * 512;
            const int r = idx >> 4, c4 = (idx & 15) << 2;
            const float M = sM[r], I = sI[r];
            float4 w;
            w.x = __expf(ra[it].x - M) * I;
            w.y = __expf(ra[it].y - M) * I;
            w.z = __expf(ra[it].z - M) * I;
            w.w = __expf(ra[it].w - M) * I;
            *(float4*)&Aw[(size_t)(row0 + r) * SS + kt + c4] = w;   // final weights
            *(float4*)&As[st * 8704 + r * 68 + c4] =
                make_float4(to_tf32(w.x), to_tf32(w.y), to_tf32(w.z), to_tf32(w.w));
        }
        #pragma unroll
        for (int it = 0; it < 2; ++it) {
            const int idx = tid + it * 512;
            const int r = idx >> 4, c4 = (idx & 15) << 2;
            *(float4*)&Bs[st * 4352 + r * 68 + c4] =
                make_float4(to_tf32(rb[it].x), to_tf32(rb[it].y),
                            to_tf32(rb[it].z), to_tf32(rb[it].w));
        }
        __syncthreads();
        // prefetch tile t+1 into regs (overlaps MMA)
        if (t + 1 < SS / 64) {
            const int kt2 = kt + 64;
            #pragma unroll
            for (int it = 0; it < 4; ++it) {
                const int idx = tid + it * 512;
                const int r = idx >> 4, c4 = (idx & 15) << 2;
                ra[it] = *(const float4*)&Aw[(size_t)(row0 + r) * SS + kt2 + c4];
            }
            #pragma unroll
            for (int it = 0; it < 2; ++it) {
                const int idx = tid + it * 512;
                const int r = idx >> 4, c4 = (idx & 15) << 2;
                rb[it] = *(const float4*)&Vv[(size_t)(kt2 + r) * DH + c4];
            }
        }
        // MMA over 64 k
        const float* Asb = As + st * 8704;
        const float* Bsb = Bs + st * 4352;
        #pragma unroll
        for (int kk = 0; kk < 8; ++kk) {
            const int kb = kk * 8;
            uint32_t a[2][4], b[2][2];
            #pragma unroll
            for (int i = 0; i < 2; ++i) {
                a[i][0] = __float_as_uint(Asb[(wm0 + 16*i + g    ) * 68 + kb + q    ]);
                a[i][1] = __float_as_uint(Asb[(wm0 + 16*i + g + 8) * 68 + kb + q    ]);
                a[i][2] = __float_as_uint(Asb[(wm0 + 16*i + g    ) * 68 + kb + q + 4]);
                a[i][3] = __float_as_uint(Asb[(wm0 + 16*i + g + 8) * 68 + kb + q + 4]);
            }
            #pragma unroll
            for (int j = 0; j < 2; ++j) {
                b[j][0] = __float_as_uint(Bsb[(kb + q    ) * 68 + wn0 + 8*j + g]);
                b[j][1] = __float_as_uint(Bsb[(kb + q + 4) * 68 + wn0 + 8*j + g]);
            }
            #pragma unroll
            for (int i = 0; i < 2; ++i)
                #pragma unroll
                for (int j = 0; j < 2; ++j)
                    MMA_TF32(acc[i][j], a[i], b[j]);
        }
        __syncthreads();
    }

    const int b = z / HH, h = z % HH;
    #pragma unroll
    for (int i = 0; i < 2; ++i) {
        #pragma unroll
        for (int rr = 0; rr < 2; ++rr) {
            const int s = row0 + wm0 + 16*i + g + rr*8;
            #pragma unroll
            for (int j = 0; j < 2; ++j) {
                const int n = wn0 + 8*j + 2*q;
                *(float2*)&Ctx[((size_t)(b*SS + s))*DD + h*64 + n] =
                    make_float2(acc[i][j][rr*2], acc[i][j][rr*2 + 1]);
            }
        }
    }
}

// ---------------------------------------------------------------------------
extern "C" void kernel_launch(void* const* d_in, const int* in_sizes, int n_in,
                              void* d_out, int out_size)
{
    const float* q       = (const float*)d_in[0];
    const float* k       = (const float*)d_in[1];
    const float* v       = (const float*)d_in[2];
    const int*   mask    = (const int*)d_in[3];
    const float* wq_w    = (const float*)d_in[4];
    const float* wq_b    = (const float*)d_in[5];
    const float* wk_w    = (const float*)d_in[6];
    const float* wk_b    = (const float*)d_in[7];
    const float* wv_w    = (const float*)d_in[8];
    const float* wv_b    = (const float*)d_in[9];
    const float* dense_w = (const float*)d_in[10];
    const float* dense_b = (const float*)d_in[11];

    float* out = (float*)d_out;
    float* wts = out + (size_t)BB * SS * DD;

    void *pQ, *pK, *pV, *pC, *pP, *pS, *pM;
    cudaGetSymbolAddress(&pQ, g_Q);
    cudaGetSymbolAddress(&pK, g_K);
    cudaGetSymbolAddress(&pV, g_V);
    cudaGetSymbolAddress(&pC, g_Ctx);
    cudaGetSymbolAddress(&pP, g_Part);
    cudaGetSymbolAddress(&pS, g_Stats);
    cudaGetSymbolAddress(&pM, g_MaskBits);
    float*    gQ = (float*)pQ;
    float*    gK = (float*)pK;
    float*    gV = (float*)pV;
    float*    gC = (float*)pC;
    float2*   gP = (float2*)pP;
    float2*   gS = (float2*)pS;
    uint32_t* gM = (uint32_t*)pM;

    const int SM_GEMM = 73728;
    const int SM_SC   = SC_SMEM_FLOATS * 4;   // 108544
    const int SM_AV   = AV_SMEM_FLOATS * 4;   // 105472
    static int inited = 0;
    if (!inited) {
        cudaFuncSetAttribute(mma_nt<0>, cudaFuncAttributeMaxDynamicSharedMemorySize, SM_GEMM);
        cudaFuncSetAttribute(mma_nt<1>, cudaFuncAttributeMaxDynamicSharedMemorySize, SM_GEMM);
        cudaFuncSetAttribute(scores_kernel, cudaFuncAttributeMaxDynamicSharedMemorySize, SM_SC);
        cudaFuncSetAttribute(mma_av, cudaFuncAttributeMaxDynamicSharedMemorySize, SM_AV);
        inited = 1;
    }

    const dim3 blk(256);

    // 0) mask -> bitmask
    maskbits_kernel<<<NWORDS / 256, 256>>>(mask, gM);

    // 1) QKV projections, one z=3 launch
    ProjArgs pa;
    pa.A[0] = q;  pa.W[0] = wq_w;  pa.bias[0] = wq_b;  pa.C[0] = gQ;
    pa.A[1] = k;  pa.W[1] = wk_w;  pa.bias[1] = wk_b;  pa.C[1] = gK;
    pa.A[2] = v;  pa.W[2] = wv_w;  pa.bias[2] = wv_b;  pa.C[2] = gV;
    const dim3 gproj(DD / 128, MROWS / 128, 3);       // (8, 32, 3)
    mma_nt<0><<<gproj, blk, SM_GEMM>>>(pa);

    // 2) Scores -> raw weights region + 4 partials/row
    const dim3 gsc(SS / 512, SS / 128, BH);           // (4, 16, 32)
    scores_kernel<<<gsc, blk, SM_SC>>>(gQ, gK, gM, wts, gP);

    // 3) Per-row stats
    reduce_stats<<<NROWTOT / 256, 256>>>(gP, gS);

    // 4) AV + in-place normalize (512 threads, KT=64)
    const dim3 gav(SS / 128, BH, 1);                  // (16, 32)
    mma_av<<<gav, 512, SM_AV>>>(wts, gV, gS, gC);

    // 5) Dense
    ProjArgs da;
    da.A[0] = gC; da.W[0] = dense_w; da.bias[0] = dense_b; da.C[0] = out;
    da.A[1] = da.A[2] = nullptr; da.W[1] = da.W[2] = nullptr;
    da.bias[1] = da.bias[2] = nullptr; da.C[1] = da.C[2] = nullptr;
    const dim3 gd(DD / 128, MROWS / 128, 1);
    mma_nt<1><<<gd, blk, SM_GEMM>>>(da);
}

// round 12
// speedup vs baseline: 1.3536x; 1.0385x over previous
#include <cuda_runtime.h>
#include <cuda_bf16.h>
#include <math.h>
#include <stdint.h>

#define BB 2
#define SS 2048
#define DD 1024
#define HH 16
#define DH 64
#define BH (BB*HH)          // 32
#define MROWS (BB*SS)       // 4096
#define NROWTOT (BH*SS)     // 65536 score rows
#define NWORDS (BB*SS*(SS/32))   // mask bit-words

// Scratch (device globals: allocation-free)
__device__ float    g_Q[BH * SS * DH];
__device__ float    g_K[BH * SS * DH];
__device__ float    g_V[BH * SS * DH];
__device__ float    g_Ctx[MROWS * DD];
__device__ float2   g_Part[(size_t)NROWTOT * 4];  // per-row per-colgroup (max, expsum)
__device__ float2   g_Stats[NROWTOT];             // per-row (max, 1/sum)
__device__ uint32_t g_MaskBits[NWORDS];           // 1 bit per mask entry

__device__ __forceinline__ float to_tf32(float x) {
    uint32_t u;
    asm("cvt.rna.tf32.f32 %0, %1;" : "=r"(u) : "f"(x));
    return __uint_as_float(u);
}
__device__ __forceinline__ uint32_t cvt_u(float x) {
    uint32_t u;
    asm("cvt.rna.tf32.f32 %0, %1;" : "=r"(u) : "f"(x));
    return u;
}

#define MMA_TF32(c, a, b)                                                     \
    asm volatile(                                                             \
        "mma.sync.aligned.m16n8k8.row.col.f32.tf32.tf32.f32 "                 \
        "{%0,%1,%2,%3},{%4,%5,%6,%7},{%8,%9},{%0,%1,%2,%3};\n"                \
        : "+f"(c[0]), "+f"(c[1]), "+f"(c[2]), "+f"(c[3])                      \
        : "r"(a[0]), "r"(a[1]), "r"(a[2]), "r"(a[3]), "r"(b[0]), "r"(b[1]))

#define CP16(dst_u32, src_ptr)                                                \
    asm volatile("cp.async.ca.shared.global [%0], [%1], 16;\n"                \
                 :: "r"(dst_u32), "l"(src_ptr))

__device__ __forceinline__ void sm_merge(float& m, float& s, float om, float os) {
    float M = fmaxf(m, om);
    float e1 = (m  > -INFINITY) ? __expf(m  - M) : 0.0f;
    float e2 = (om > -INFINITY) ? __expf(om - M) : 0.0f;
    s = s * e1 + os * e2;
    m = M;
}

struct ProjArgs {
    const float* A[3];
    const float* W[3];
    const float* bias[3];
    float* C[3];
};

// ---------------------------------------------------------------------------
// Mask int32 -> bitmask. One thread per 32-entry word.
// ---------------------------------------------------------------------------
__global__ __launch_bounds__(256)
void maskbits_kernel(const int* __restrict__ mask, uint32_t* __restrict__ bits)
{
    const int w = blockIdx.x * 256 + threadIdx.x;
    const int* p = mask + (size_t)w * 32;
    uint32_t m = 0;
    #pragma unroll
    for (int c = 0; c < 8; ++c) {
        int4 v = *(const int4*)&p[c * 4];
        m |= (uint32_t)(v.x != 0) << (c*4    );
        m |= (uint32_t)(v.y != 0) << (c*4 + 1);
        m |= (uint32_t)(v.z != 0) << (c*4 + 2);
        m |= (uint32_t)(v.w != 0) << (c*4 + 3);
    }
    bits[w] = m;
}

// ---------------------------------------------------------------------------
// TF32 MMA GEMM with cp.async 2-stage pipeline: C = A*B^T + bias.
// BM=BN=128, BK=32, 256 thr, warp tile 64x32.
// MODE 0: proj, z-indexed (scatter to [B,H,S,DH]) | MODE 1: dense
// ---------------------------------------------------------------------------
template<int MODE>
__global__ __launch_bounds__(256, 2)
void mma_nt(ProjArgs pa)
{
    extern __shared__ float sm[];
    float* pA = sm;               // 2 stages x 128x36
    float* pB = sm + 2 * 4608;

    const int zi = (MODE == 0) ? blockIdx.z : 0;
    const float* A    = pa.A[zi];
    const float* Bw   = pa.W[zi];
    const float* bias = pa.bias[zi];
    float* C          = pa.C[zi];

    const int tid = threadIdx.x;
    const int wid = tid >> 5, lane = tid & 31;
    const int g = lane >> 2, q = lane & 3;
    const int wm0 = (wid >> 2) * 64;
    const int wn0 = (wid & 3) * 32;
    const int row0 = blockIdx.y * 128;
    const int col0 = blockIdx.x * 128;
    const int K = DD;

    uint32_t sA = (uint32_t)__cvta_generic_to_shared(pA);
    uint32_t sB = (uint32_t)__cvta_generic_to_shared(pB);

    float acc[4][4][4];
    #pragma unroll
    for (int i = 0; i < 4; ++i)
        #pragma unroll
        for (int j = 0; j < 4; ++j)
            #pragma unroll
            for (int r = 0; r < 4; ++r) acc[i][j][r] = 0.0f;

    auto copy_tile = [&](int st, int kt) {
        #pragma unroll
        for (int it = 0; it < 4; ++it) {
            const int idx = tid + it * 256;
            const int r = idx >> 3, c4 = (idx & 7) << 2;
            CP16(sA + (uint32_t)(st * 4608 + r * 36 + c4) * 4,
                 &A[(size_t)(row0 + r) * K + kt + c4]);
            CP16(sB + (uint32_t)(st * 4608 + r * 36 + c4) * 4,
                 &Bw[(size_t)(col0 + r) * K + kt + c4]);
        }
        asm volatile("cp.async.commit_group;\n");
    };

    copy_tile(0, 0);
    const int T = K / 32;
    for (int t = 0; t < T; ++t) {
        if (t + 1 < T) {
            copy_tile((t + 1) & 1, (t + 1) * 32);
            asm volatile("cp.async.wait_group 1;\n");
        } else {
            asm volatile("cp.async.wait_group 0;\n");
        }
        __syncthreads();
        const float* Asb = pA + (t & 1) * 4608;
        const float* Bsb = pB + (t & 1) * 4608;
        #pragma unroll
        for (int kk = 0; kk < 4; ++kk) {
            const int kb = kk * 8;
            uint32_t a[4][4], b[4][2];
            #pragma unroll
            for (int i = 0; i < 4; ++i) {
                a[i][0] = cvt_u(Asb[(wm0 + 16*i + g    ) * 36 + kb + q    ]);
                a[i][1] = cvt_u(Asb[(wm0 + 16*i + g + 8) * 36 + kb + q    ]);
                a[i][2] = cvt_u(Asb[(wm0 + 16*i + g    ) * 36 + kb + q + 4]);
                a[i][3] = cvt_u(Asb[(wm0 + 16*i + g + 8) * 36 + kb + q + 4]);
            }
            #pragma unroll
            for (int j = 0; j < 4; ++j) {
                b[j][0] = cvt_u(Bsb[(wn0 + 8*j + g) * 36 + kb + q    ]);
                b[j][1] = cvt_u(Bsb[(wn0 + 8*j + g) * 36 + kb + q + 4]);
            }
            #pragma unroll
            for (int i = 0; i < 4; ++i)
                #pragma unroll
                for (int j = 0; j < 4; ++j)
                    MMA_TF32(acc[i][j], a[i], b[j]);
        }
        __syncthreads();
    }

    #pragma unroll
    for (int i = 0; i < 4; ++i) {
        #pragma unroll
        for (int rr = 0; rr < 2; ++rr) {
            const int gr = row0 + wm0 + 16*i + g + rr*8;
            #pragma unroll
            for (int j = 0; j < 4; ++j) {
                const int gc = col0 + wn0 + 8*j + 2*q;
                const float v0 = acc[i][j][rr*2 + 0];
                const float v1 = acc[i][j][rr*2 + 1];
                float2 bv = *(const float2*)&bias[gc];
                if (MODE == 0) {
                    const int b = gr >> 11, s = gr & 2047;
                    const int h = gc >> 6, d = gc & 63;
                    *(float2*)&C[(((size_t)(b*HH + h))*SS + s)*DH + d] =
                        make_float2(v0 + bv.x, v1 + bv.y);
                } else {
                    *(float2*)&C[(size_t)gr * DD + gc] =
                        make_float2(v0 + bv.x, v1 + bv.y);
                }
            }
        }
    }
}

// ---------------------------------------------------------------------------
// Scores v2: per (z, row-block, col-group of 512): Q tile resident, loop 4
// K tiles with cp.async double-buffer. Masked raw scores -> weights region
// (fragment writes), online per-row (max, expsum) across the 4 tiles ->
// g_Part[row][colgroup]. Bitmask for mask tests.
// ---------------------------------------------------------------------------
#define SC_SMEM_FLOATS (8704 + 2*8704 + 512 + 512)

__global__ __launch_bounds__(256, 2)
void scores_kernel(const float* __restrict__ Q, const float* __restrict__ Kh,
                   const uint32_t* __restrict__ mbits, float* __restrict__ Wraw,
                   float2* __restrict__ Part)
{
    extern __shared__ float sm[];
    float* sQ = sm;                      // 128 x 68
    float* sK = sm + 8704;               // 2 x 128 x 68
    float* red_m = sm + 8704 + 17408;    // 128 x 4
    float* red_s = red_m + 512;          // 128 x 4

    const int tid = threadIdx.x;
    const int wid = tid >> 5, lane = tid & 31;
    const int g = lane >> 2, q = lane & 3;
    const int wm0 = (wid >> 2) * 64;
    const int wn0 = (wid & 3) * 32;
    const int wc  = wid & 3;
    const int z = blockIdx.z;
    const int row0 = blockIdx.y * 128;
    const int cg0 = blockIdx.x * 512;

    const float* Qz = Q  + (size_t)z * SS * DH;
    const float* Kz = Kh + (size_t)z * SS * DH;
    float* Cz = Wraw + (size_t)z * SS * SS;
    const uint32_t* mrow0 = mbits + (size_t)(z >> 4) * SS * (SS/32);

    uint32_t sQa = (uint32_t)__cvta_generic_to_shared(sQ);
    uint32_t sKa = (uint32_t)__cvta_generic_to_shared(sK);

    // Prologue: Q + K0 (group), K1 (group)
    {
        #pragma unroll
        for (int it = 0; it < 8; ++it) {
            const int idx = tid + it * 256;
            const int r = idx >> 4, c4 = (idx & 15) << 2;
            CP16(sQa + (uint32_t)(r * 68 + c4) * 4,
                 &Qz[(size_t)(row0 + r) * DH + c4]);
            CP16(sKa + (uint32_t)(r * 68 + c4) * 4,
                 &Kz[(size_t)(cg0 + r) * DH + c4]);
        }
        asm volatile("cp.async.commit_group;\n");
        #pragma unroll
        for (int it = 0; it < 8; ++it) {
            const int idx = tid + it * 256;
            const int r = idx >> 4, c4 = (idx & 15) << 2;
            CP16(sKa + (uint32_t)(8704 + r * 68 + c4) * 4,
                 &Kz[(size_t)(cg0 + 128 + r) * DH + c4]);
        }
        asm volatile("cp.async.commit_group;\n");
    }

    float m8[4][2], s8[4][2];
    #pragma unroll
    for (int i = 0; i < 4; ++i)
        #pragma unroll
        for (int rr = 0; rr < 2; ++rr) { m8[i][rr] = -INFINITY; s8[i][rr] = 0.0f; }

    for (int t = 0; t < 4; ++t) {
        if (t < 3) {
            asm volatile("cp.async.wait_group 1;\n");
        } else {
            asm volatile("cp.async.wait_group 0;\n");
        }
        __syncthreads();

        const float* Ksb = sK + (t & 1) * 8704;
        float acc[4][4][4];
        #pragma unroll
        for (int i = 0; i < 4; ++i)
            #pragma unroll
            for (int j = 0; j < 4; ++j)
                #pragma unroll
                for (int r = 0; r < 4; ++r) acc[i][j][r] = 0.0f;

        #pragma unroll
        for (int kk = 0; kk < 8; ++kk) {
            const int kb = kk * 8;
            uint32_t a[4][4], b[4][2];
            #pragma unroll
            for (int i = 0; i < 4; ++i) {
                a[i][0] = cvt_u(sQ[(wm0 + 16*i + g    ) * 68 + kb + q    ]);
                a[i][1] = cvt_u(sQ[(wm0 + 16*i + g + 8) * 68 + kb + q    ]);
                a[i][2] = cvt_u(sQ[(wm0 + 16*i + g    ) * 68 + kb + q + 4]);
                a[i][3] = cvt_u(sQ[(wm0 + 16*i + g + 8) * 68 + kb + q + 4]);
            }
            #pragma unroll
            for (int j = 0; j < 4; ++j) {
                b[j][0] = cvt_u(Ksb[(wn0 + 8*j + g) * 68 + kb + q    ]);
                b[j][1] = cvt_u(Ksb[(wn0 + 8*j + g) * 68 + kb + q + 4]);
            }
            #pragma unroll
            for (int i = 0; i < 4; ++i)
                #pragma unroll
                for (int j = 0; j < 4; ++j)
                    MMA_TF32(acc[i][j], a[i], b[j]);
        }
        __syncthreads();

        // issue load for tile t+2 into the buffer just freed
        if (t + 2 < 4) {
            const int dst = (t & 1) * 8704;
            #pragma unroll
            for (int it = 0; it < 8; ++it) {
                const int idx = tid + it * 256;
                const int r = idx >> 4, c4 = (idx & 15) << 2;
                CP16(sKa + (uint32_t)(dst + r * 68 + c4) * 4,
                     &Kz[(size_t)(cg0 + (t + 2) * 128 + r) * DH + c4]);
            }
            asm volatile("cp.async.commit_group;\n");
        }

        // Epilogue (overlaps in-flight load): bitmask + write + online stats
        const int colb = cg0 + t * 128 + wn0;      // warp's 32-col span base
        const int wword = colb >> 5;
        #pragma unroll
        for (int i = 0; i < 4; ++i) {
            #pragma unroll
            for (int rr = 0; rr < 2; ++rr) {
                const int gr = row0 + wm0 + 16*i + g + rr*8;
                const uint32_t mw = mrow0[(size_t)gr * (SS/32) + wword];
                float vals[8];
                float mt = -INFINITY;
                #pragma unroll
                for (int j = 0; j < 4; ++j) {
                    const int cl = 8*j + 2*q;
                    float v0 = (mw >> cl) & 1u ? acc[i][j][rr*2    ] * 0.125f : -INFINITY;
                    float v1 = (mw >> (cl+1)) & 1u ? acc[i][j][rr*2 + 1] * 0.125f : -INFINITY;
                    *(float2*)&Cz[(size_t)gr * SS + colb + cl] = make_float2(v0, v1);
                    vals[j*2] = v0; vals[j*2+1] = v1;
                    mt = fmaxf(mt, fmaxf(v0, v1));
                }
                const float Mn = fmaxf(m8[i][rr], mt);
                if (Mn > -INFINITY) {
                    float add = 0.0f;
                    #pragma unroll
                    for (int e = 0; e < 8; ++e)
                        add += (vals[e] > -INFINITY) ? __expf(vals[e] - Mn) : 0.0f;
                    const float keep = (m8[i][rr] > -INFINITY)
                                     ? s8[i][rr] * __expf(m8[i][rr] - Mn) : 0.0f;
                    s8[i][rr] = keep + add;
                    m8[i][rr] = Mn;
                }
            }
        }
    }

    // reduce stats: across q lanes, then across 4 col-warps
    #pragma unroll
    for (int i = 0; i < 4; ++i) {
        #pragma unroll
        for (int rr = 0; rr < 2; ++rr) {
            float m = m8[i][rr], s = s8[i][rr];
            #pragma unroll
            for (int o = 1; o <= 2; o <<= 1) {
                float om = __shfl_xor_sync(0xffffffffu, m, o);
                float os = __shfl_xor_sync(0xffffffffu, s, o);
                sm_merge(m, s, om, os);
            }
            if (q == 0) {
                const int R = wm0 + 16*i + g + rr*8;
                red_m[R * 4 + wc] = m;
                red_s[R * 4 + wc] = s;
            }
        }
    }
    __syncthreads();
    if (tid < 128) {
        float m = red_m[tid * 4], s = red_s[tid * 4];
        #pragma unroll
        for (int w = 1; w < 4; ++w)
            sm_merge(m, s, red_m[tid * 4 + w], red_s[tid * 4 + w]);
        Part[((size_t)z * SS + row0 + tid) * 4 + blockIdx.x] = make_float2(m, s);
    }
}

// ---------------------------------------------------------------------------
// Reduce partials -> per-row (max, 1/sum)
// ---------------------------------------------------------------------------
__global__ __launch_bounds__(256)
void reduce_stats(const float2* __restrict__ Part, float2* __restrict__ Stats)
{
    const int row = blockIdx.x * 256 + threadIdx.x;
    float2 p[4];
    #pragma unroll
    for (int i = 0; i < 4; ++i) p[i] = Part[(size_t)row * 4 + i];
    float M = -INFINITY;
    #pragma unroll
    for (int i = 0; i < 4; ++i) M = fmaxf(M, p[i].x);
    float S = 0.0f;
    #pragma unroll
    for (int i = 0; i < 4; ++i)
        S += (p[i].x > -INFINITY) ? p[i].y * __expf(p[i].x - M) : 0.0f;
    Stats[row] = make_float2(M, (S > 0.0f) ? 1.0f / S : 0.0f);
}

// ---------------------------------------------------------------------------
// AV fused with softmax-apply: 512 threads, KT=64 per iter (32 iters,
// 1 sync/iter). Reads raw scores, w=exp(x-M)*invS, writes weights in place
// (per-thread RMW of its own addresses -> race-free), accumulates W@V.
// Warp tile 32x16 (4x4 warp grid).
// ---------------------------------------------------------------------------
#define AV_SMEM_FLOATS (2*8704 + 2*4352 + 256)

__global__ __launch_bounds__(512, 1)
void mma_av(float* __restrict__ Wts, const float* __restrict__ Vh,
            const float2* __restrict__ Stats, float* __restrict__ Ctx)
{
    extern __shared__ float sm[];
    float* As = sm;                    // [2][128][68]
    float* Bs = sm + 2 * 8704;         // [2][64][68]
    float* sM = sm + 2 * 8704 + 2 * 4352;
    float* sI = sM + 128;

    const int z = blockIdx.y;
    float* Aw = Wts + (size_t)z * SS * SS;
    const float* Vv = Vh + (size_t)z * SS * DH;
    const int row0 = blockIdx.x * 128;

    const int tid = threadIdx.x;
    const int wid = tid >> 5, lane = tid & 31;
    const int g = lane >> 2, q = lane & 3;
    const int wm0 = (wid >> 2) * 32;   // 4 row groups
    const int wn0 = (wid & 3) * 16;    // 4 col groups

    if (tid < 128) {
        float2 st = Stats[(size_t)z * SS + row0 + tid];
        sM[tid] = st.x; sI[tid] = st.y;
    }

    float acc[2][2][4];
    #pragma unroll
    for (int i = 0; i < 2; ++i)
        #pragma unroll
        for (int j = 0; j < 2; ++j)
            #pragma unroll
            for (int r = 0; r < 4; ++r) acc[i][j][r] = 0.0f;

    // prologue loads (tile 0): A 128x64, V 64x64
    float4 ra[4], rb[2];
    #pragma unroll
    for (int it = 0; it < 4; ++it) {
        const int idx = tid + it * 512;
        const int r = idx >> 4, c4 = (idx & 15) << 2;
        ra[it] = *(const float4*)&Aw[(size_t)(row0 + r) * SS + c4];
    }
    #pragma unroll
    for (int it = 0; it < 2; ++it) {
        const int idx = tid + it * 512;
        const int r = idx >> 4, c4 = (idx & 15) << 2;
        rb[it] = *(const float4*)&Vv[(size_t)r * DH + c4];
    }
    __syncthreads();   // stats visible

    for (int t = 0; t < SS / 64; ++t) {
        const int kt = t * 64;
        const int st = t & 1;
        // transform + stage tile t; write normalized weights to gmem
        #pragma unroll
        for (int it = 0; it < 4; ++it) {
            const int idx = tid + it * 512;
            const int r = idx >> 4, c4 = (idx & 15) << 2;
            const float M = sM[r], I = sI[r];
            float4 w;
            w.x = __expf(ra[it].x - M) * I;
            w.y = __expf(ra[it].y - M) * I;
            w.z = __expf(ra[it].z - M) * I;
            w.w = __expf(ra[it].w - M) * I;
            *(float4*)&Aw[(size_t)(row0 + r) * SS + kt + c4] = w;   // final weights
            *(float4*)&As[st * 8704 + r * 68 + c4] =
                make_float4(to_tf32(w.x), to_tf32(w.y), to_tf32(w.z), to_tf32(w.w));
        }
        #pragma unroll
        for (int it = 0; it < 2; ++it) {
            const int idx = tid + it * 512;
            const int r = idx >> 4, c4 = (idx & 15) << 2;
            *(float4*)&Bs[st * 4352 + r * 68 + c4] =
                make_float4(to_tf32(rb[it].x), to_tf32(rb[it].y),
                            to_tf32(rb[it].z), to_tf32(rb[it].w));
        }
        __syncthreads();
        // prefetch tile t+1 into regs (overlaps MMA)
        if (t + 1 < SS / 64) {
            const int kt2 = kt + 64;
            #pragma unroll
            for (int it = 0; it < 4; ++it) {
                const int idx = tid + it * 512;
                const int r = idx >> 4, c4 = (idx & 15) << 2;
                ra[it] = *(const float4*)&Aw[(size_t)(row0 + r) * SS + kt2 + c4];
            }
            #pragma unroll
            for (int it = 0; it < 2; ++it) {
                const int idx = tid + it * 512;
                const int r = idx >> 4, c4 = (idx & 15) << 2;
                rb[it] = *(const float4*)&Vv[(size_t)(kt2 + r) * DH + c4];
            }
        }
        // MMA over 64 k
        const float* Asb = As + st * 8704;
        const float* Bsb = Bs + st * 4352;
        #pragma unroll
        for (int kk = 0; kk < 8; ++kk) {
            const int kb = kk * 8;
            uint32_t a[2][4], b[2][2];
            #pragma unroll
            for (int i = 0; i < 2; ++i) {
                a[i][0] = __float_as_uint(Asb[(wm0 + 16*i + g    ) * 68 + kb + q    ]);
                a[i][1] = __float_as_uint(Asb[(wm0 + 16*i + g + 8) * 68 + kb + q    ]);
                a[i][2] = __float_as_uint(Asb[(wm0 + 16*i + g    ) * 68 + kb + q + 4]);
                a[i][3] = __float_as_uint(Asb[(wm0 + 16*i + g + 8) * 68 + kb + q + 4]);
            }
            #pragma unroll
            for (int j = 0; j < 2; ++j) {
                b[j][0] = __float_as_uint(Bsb[(kb + q    ) * 68 + wn0 + 8*j + g]);
                b[j][1] = __float_as_uint(Bsb[(kb + q + 4) * 68 + wn0 + 8*j + g]);
            }
            #pragma unroll
            for (int i = 0; i < 2; ++i)
                #pragma unroll
                for (int j = 0; j < 2; ++j)
                    MMA_TF32(acc[i][j], a[i], b[j]);
        }
        __syncthreads();
    }

    const int b = z / HH, h = z % HH;
    #pragma unroll
    for (int i = 0; i < 2; ++i) {
        #pragma unroll
        for (int rr = 0; rr < 2; ++rr) {
            const int s = row0 + wm0 + 16*i + g + rr*8;
            #pragma unroll
            for (int j = 0; j < 2; ++j) {
                const int n = wn0 + 8*j + 2*q;
                *(float2*)&Ctx[((size_t)(b*SS + s))*DD + h*64 + n] =
                    make_float2(acc[i][j][rr*2], acc[i][j][rr*2 + 1]);
            }
        }
    }
}

// ---------------------------------------------------------------------------
extern "C" void kernel_launch(void* const* d_in, const int* in_sizes, int n_in,
                              void* d_out, int out_size)
{
    const float* q       = (const float*)d_in[0];
    const float* k       = (const float*)d_in[1];
    const float* v       = (const float*)d_in[2];
    const int*   mask    = (const int*)d_in[3];
    const float* wq_w    = (const float*)d_in[4];
    const float* wq_b    = (const float*)d_in[5];
    const float* wk_w    = (const float*)d_in[6];
    const float* wk_b    = (const float*)d_in[7];
    const float* wv_w    = (const float*)d_in[8];
    const float* wv_b    = (const float*)d_in[9];
    const float* dense_w = (const float*)d_in[10];
    const float* dense_b = (const float*)d_in[11];

    float* out = (float*)d_out;
    float* wts = out + (size_t)BB * SS * DD;

    void *pQ, *pK, *pV, *pC, *pP, *pS, *pM;
    cudaGetSymbolAddress(&pQ, g_Q);
    cudaGetSymbolAddress(&pK, g_K);
    cudaGetSymbolAddress(&pV, g_V);
    cudaGetSymbolAddress(&pC, g_Ctx);
    cudaGetSymbolAddress(&pP, g_Part);
    cudaGetSymbolAddress(&pS, g_Stats);
    cudaGetSymbolAddress(&pM, g_MaskBits);
    float*    gQ = (float*)pQ;
    float*    gK = (float*)pK;
    float*    gV = (float*)pV;
    float*    gC = (float*)pC;
    float2*   gP = (float2*)pP;
    float2*   gS = (float2*)pS;
    uint32_t* gM = (uint32_t*)pM;

    const int SM_GEMM = 73728;
    const int SM_SC   = SC_SMEM_FLOATS * 4;   // 108544
    const int SM_AV   = AV_SMEM_FLOATS * 4;   // 105472

    static cudaStream_t s1;
    static cudaEvent_t evRoot, evM, evV;
    static int inited = 0;
    if (!inited) {
        cudaFuncSetAttribute(mma_nt<0>, cudaFuncAttributeMaxDynamicSharedMemorySize, SM_GEMM);
        cudaFuncSetAttribute(mma_nt<1>, cudaFuncAttributeMaxDynamicSharedMemorySize, SM_GEMM);
        cudaFuncSetAttribute(scores_kernel, cudaFuncAttributeMaxDynamicSharedMemorySize, SM_SC);
        cudaFuncSetAttribute(mma_av, cudaFuncAttributeMaxDynamicSharedMemorySize, SM_AV);
        cudaStreamCreateWithFlags(&s1, cudaStreamNonBlocking);
        cudaEventCreateWithFlags(&evRoot, cudaEventDisableTiming);
        cudaEventCreateWithFlags(&evM, cudaEventDisableTiming);
        cudaEventCreateWithFlags(&evV, cudaEventDisableTiming);
        inited = 1;
    }

    const dim3 blk(256);

    // Fork side stream off the capture origin
    cudaEventRecord(evRoot, 0);
    cudaStreamWaitEvent(s1, evRoot, 0);

    // side stream: maskbits, then V projection
    maskbits_kernel<<<NWORDS / 256, 256, 0, s1>>>(mask, gM);
    cudaEventRecord(evM, s1);
    {
        ProjArgs pv;
        pv.A[0] = v;  pv.W[0] = wv_w;  pv.bias[0] = wv_b;  pv.C[0] = gV;
        pv.A[1] = pv.A[2] = v; pv.W[1] = pv.W[2] = wv_w;
        pv.bias[1] = pv.bias[2] = wv_b; pv.C[1] = pv.C[2] = gV;
        const dim3 gpv(DD / 128, MROWS / 128, 1);
        mma_nt<0><<<gpv, blk, SM_GEMM, s1>>>(pv);
    }
    cudaEventRecord(evV, s1);

    // default stream: Q,K projections (z=2)
    {
        ProjArgs pqk;
        pqk.A[0] = q;  pqk.W[0] = wq_w;  pqk.bias[0] = wq_b;  pqk.C[0] = gQ;
        pqk.A[1] = k;  pqk.W[1] = wk_w;  pqk.bias[1] = wk_b;  pqk.C[1] = gK;
        pqk.A[2] = q;  pqk.W[2] = wq_w;  pqk.bias[2] = wq_b;  pqk.C[2] = gQ;
        const dim3 gqk(DD / 128, MROWS / 128, 2);
        mma_nt<0><<<gqk, blk, SM_GEMM>>>(pqk);
    }

    // scores needs maskbits
    cudaStreamWaitEvent(0, evM, 0);
    const dim3 gsc(SS / 512, SS / 128, BH);           // (4, 16, 32)
    scores_kernel<<<gsc, blk, SM_SC>>>(gQ, gK, gM, wts, gP);

    reduce_stats<<<NROWTOT / 256, 256>>>(gP, gS);

    // mma_av needs V projection
    cudaStreamWaitEvent(0, evV, 0);
    const dim3 gav(SS / 128, BH, 1);                  // (16, 32)
    mma_av<<<gav, 512, SM_AV>>>(wts, gV, gS, gC);

    // dense
    {
        ProjArgs da;
        da.A[0] = gC; da.W[0] = dense_w; da.bias[0] = dense_b; da.C[0] = out;
        da.A[1] = da.A[2] = gC; da.W[1] = da.W[2] = dense_w;
        da.bias[1] = da.bias[2] = dense_b; da.C[1] = da.C[2] = out;
        const dim3 gd(DD / 128, MROWS / 128, 1);
        mma_nt<1><<<gd, blk, SM_GEMM>>>(da);
    }
}

// round 14
// speedup vs baseline: 1.4437x; 1.0666x over previous
#include <cuda_runtime.h>
#include <cuda_bf16.h>
#include <math.h>
#include <stdint.h>

#define BB 2
#define SS 2048
#define DD 1024
#define HH 16
#define DH 64
#define BH (BB*HH)          // 32
#define MROWS (BB*SS)       // 4096
#define NROWTOT (BH*SS)     // 65536 score rows
#define NWORDS (BB*SS*(SS/32))   // mask bit-words

// Scratch (device globals: allocation-free)
__device__ float    g_Q[BH * SS * DH];
__device__ float    g_K[BH * SS * DH];
__device__ float    g_V[BH * SS * DH];
__device__ float    g_Ctx[MROWS * DD];
__device__ float    g_Part[(size_t)NROWTOT * 4];  // per-row per-colgroup expsum
__device__ float    g_InvS[NROWTOT];              // per-row 1/sum
__device__ uint32_t g_MaskBits[NWORDS];           // 1 bit per mask entry

__device__ __forceinline__ float to_tf32(float x) {
    uint32_t u;
    asm("cvt.rna.tf32.f32 %0, %1;" : "=r"(u) : "f"(x));
    return __uint_as_float(u);
}
__device__ __forceinline__ uint32_t cvt_u(float x) {
    uint32_t u;
    asm("cvt.rna.tf32.f32 %0, %1;" : "=r"(u) : "f"(x));
    return u;
}

#define MMA_TF32(c, a, b)                                                     \
    asm volatile(                                                             \
        "mma.sync.aligned.m16n8k8.row.col.f32.tf32.tf32.f32 "                 \
        "{%0,%1,%2,%3},{%4,%5,%6,%7},{%8,%9},{%0,%1,%2,%3};\n"                \
        : "+f"(c[0]), "+f"(c[1]), "+f"(c[2]), "+f"(c[3])                      \
        : "r"(a[0]), "r"(a[1]), "r"(a[2]), "r"(a[3]), "r"(b[0]), "r"(b[1]))

#define CP16(dst_u32, src_ptr)                                                \
    asm volatile("cp.async.ca.shared.global [%0], [%1], 16;\n"                \
                 :: "r"(dst_u32), "l"(src_ptr))

struct ProjArgs {
    const float* A[3];
    const float* W[3];
    const float* bias[3];
    float* C[3];
};

// ---------------------------------------------------------------------------
// Mask int32 -> bitmask. One thread per 32-entry word.
// ---------------------------------------------------------------------------
__global__ __launch_bounds__(256)
void maskbits_kernel(const int* __restrict__ mask, uint32_t* __restrict__ bits)
{
    const int w = blockIdx.x * 256 + threadIdx.x;
    const int* p = mask + (size_t)w * 32;
    uint32_t m = 0;
    #pragma unroll
    for (int c = 0; c < 8; ++c) {
        int4 v = *(const int4*)&p[c * 4];
        m |= (uint32_t)(v.x != 0) << (c*4    );
        m |= (uint32_t)(v.y != 0) << (c*4 + 1);
        m |= (uint32_t)(v.z != 0) << (c*4 + 2);
        m |= (uint32_t)(v.w != 0) << (c*4 + 3);
    }
    bits[w] = m;
}

// ---------------------------------------------------------------------------
// TF32 MMA GEMM with cp.async 2-stage pipeline: C = A*B^T + bias.
// BM=BN=128, BK=32, 256 thr, warp tile 64x32.
// MODE 0: proj, z-indexed (scatter to [B,H,S,DH]) | MODE 1: dense
// ---------------------------------------------------------------------------
template<int MODE>
__global__ __launch_bounds__(256, 2)
void mma_nt(ProjArgs pa)
{
    extern __shared__ float sm[];
    float* pA = sm;               // 2 stages x 128x36
    float* pB = sm + 2 * 4608;

    const int zi = (MODE == 0) ? blockIdx.z : 0;
    const float* A    = pa.A[zi];
    const float* Bw   = pa.W[zi];
    const float* bias = pa.bias[zi];
    float* C          = pa.C[zi];

    const int tid = threadIdx.x;
    const int wid = tid >> 5, lane = tid & 31;
    const int g = lane >> 2, q = lane & 3;
    const int wm0 = (wid >> 2) * 64;
    const int wn0 = (wid & 3) * 32;
    const int row0 = blockIdx.y * 128;
    const int col0 = blockIdx.x * 128;
    const int K = DD;

    uint32_t sA = (uint32_t)__cvta_generic_to_shared(pA);
    uint32_t sB = (uint32_t)__cvta_generic_to_shared(pB);

    float acc[4][4][4];
    #pragma unroll
    for (int i = 0; i < 4; ++i)
        #pragma unroll
        for (int j = 0; j < 4; ++j)
            #pragma unroll
            for (int r = 0; r < 4; ++r) acc[i][j][r] = 0.0f;

    auto copy_tile = [&](int st, int kt) {
        #pragma unroll
        for (int it = 0; it < 4; ++it) {
            const int idx = tid + it * 256;
            const int r = idx >> 3, c4 = (idx & 7) << 2;
            CP16(sA + (uint32_t)(st * 4608 + r * 36 + c4) * 4,
                 &A[(size_t)(row0 + r) * K + kt + c4]);
            CP16(sB + (uint32_t)(st * 4608 + r * 36 + c4) * 4,
                 &Bw[(size_t)(col0 + r) * K + kt + c4]);
        }
        asm volatile("cp.async.commit_group;\n");
    };

    copy_tile(0, 0);
    const int T = K / 32;
    for (int t = 0; t < T; ++t) {
        if (t + 1 < T) {
            copy_tile((t + 1) & 1, (t + 1) * 32);
            asm volatile("cp.async.wait_group 1;\n");
        } else {
            asm volatile("cp.async.wait_group 0;\n");
        }
        __syncthreads();
        const float* Asb = pA + (t & 1) * 4608;
        const float* Bsb = pB + (t & 1) * 4608;
        #pragma unroll
        for (int kk = 0; kk < 4; ++kk) {
            const int kb = kk * 8;
            uint32_t a[4][4], b[4][2];
            #pragma unroll
            for (int i = 0; i < 4; ++i) {
                a[i][0] = cvt_u(Asb[(wm0 + 16*i + g    ) * 36 + kb + q    ]);
                a[i][1] = cvt_u(Asb[(wm0 + 16*i + g + 8) * 36 + kb + q    ]);
                a[i][2] = cvt_u(Asb[(wm0 + 16*i + g    ) * 36 + kb + q + 4]);
                a[i][3] = cvt_u(Asb[(wm0 + 16*i + g + 8) * 36 + kb + q + 4]);
            }
            #pragma unroll
            for (int j = 0; j < 4; ++j) {
                b[j][0] = cvt_u(Bsb[(wn0 + 8*j + g) * 36 + kb + q    ]);
                b[j][1] = cvt_u(Bsb[(wn0 + 8*j + g) * 36 + kb + q + 4]);
            }
            #pragma unroll
            for (int i = 0; i < 4; ++i)
                #pragma unroll
                for (int j = 0; j < 4; ++j)
                    MMA_TF32(acc[i][j], a[i], b[j]);
        }
        __syncthreads();
    }

    #pragma unroll
    for (int i = 0; i < 4; ++i) {
        #pragma unroll
        for (int rr = 0; rr < 2; ++rr) {
            const int gr = row0 + wm0 + 16*i + g + rr*8;
            #pragma unroll
            for (int j = 0; j < 4; ++j) {
                const int gc = col0 + wn0 + 8*j + 2*q;
                const float v0 = acc[i][j][rr*2 + 0];
                const float v1 = acc[i][j][rr*2 + 1];
                float2 bv = *(const float2*)&bias[gc];
                if (MODE == 0) {
                    const int b = gr >> 11, s = gr & 2047;
                    const int h = gc >> 6, d = gc & 63;
                    *(float2*)&C[(((size_t)(b*HH + h))*SS + s)*DH + d] =
                        make_float2(v0 + bv.x, v1 + bv.y);
                } else {
                    *(float2*)&C[(size_t)gr * DD + gc] =
                        make_float2(v0 + bv.x, v1 + bv.y);
                }
            }
        }
    }
}

// ---------------------------------------------------------------------------
// Scores v3: per (z, row-block, col-group of 512): Q resident, 4 K tiles
// cp.async double-buffered. Writes e = exp(s*0.125)*maskbit (unnormalized,
// no max subtraction — scores bounded ~|8| so fp32-safe) into weights
// region; accumulates plain per-row expsum -> g_Part[row][colgroup].
// ---------------------------------------------------------------------------
#define SC_SMEM_FLOATS (8704 + 2*8704 + 512)

__global__ __launch_bounds__(256, 2)
void scores_kernel(const float* __restrict__ Q, const float* __restrict__ Kh,
                   const uint32_t* __restrict__ mbits, float* __restrict__ Wraw,
                   float* __restrict__ Part)
{
    extern __shared__ float sm[];
    float* sQ = sm;                      // 128 x 68
    float* sK = sm + 8704;               // 2 x 128 x 68
    float* red_s = sm + 8704 + 17408;    // 128 x 4

    const int tid = threadIdx.x;
    const int wid = tid >> 5, lane = tid & 31;
    const int g = lane >> 2, q = lane & 3;
    const int wm0 = (wid >> 2) * 64;
    const int wn0 = (wid & 3) * 32;
    const int wc  = wid & 3;
    const int z = blockIdx.z;
    const int row0 = blockIdx.y * 128;
    const int cg0 = blockIdx.x * 512;

    const float* Qz = Q  + (size_t)z * SS * DH;
    const float* Kz = Kh + (size_t)z * SS * DH;
    float* Cz = Wraw + (size_t)z * SS * SS;
    const uint32_t* mrow0 = mbits + (size_t)(z >> 4) * SS * (SS/32);

    uint32_t sQa = (uint32_t)__cvta_generic_to_shared(sQ);
    uint32_t sKa = (uint32_t)__cvta_generic_to_shared(sK);

    // Prologue: Q + K0, K1
    {
        #pragma unroll
        for (int it = 0; it < 8; ++it) {
            const int idx = tid + it * 256;
            const int r = idx >> 4, c4 = (idx & 15) << 2;
            CP16(sQa + (uint32_t)(r * 68 + c4) * 4,
                 &Qz[(size_t)(row0 + r) * DH + c4]);
            CP16(sKa + (uint32_t)(r * 68 + c4) * 4,
                 &Kz[(size_t)(cg0 + r) * DH + c4]);
        }
        asm volatile("cp.async.commit_group;\n");
        #pragma unroll
        for (int it = 0; it < 8; ++it) {
            const int idx = tid + it * 256;
            const int r = idx >> 4, c4 = (idx & 15) << 2;
            CP16(sKa + (uint32_t)(8704 + r * 68 + c4) * 4,
                 &Kz[(size_t)(cg0 + 128 + r) * DH + c4]);
        }
        asm volatile("cp.async.commit_group;\n");
    }

    float s8[4][2];
    #pragma unroll
    for (int i = 0; i < 4; ++i)
        #pragma unroll
        for (int rr = 0; rr < 2; ++rr) s8[i][rr] = 0.0f;

    for (int t = 0; t < 4; ++t) {
        if (t < 3) {
            asm volatile("cp.async.wait_group 1;\n");
        } else {
            asm volatile("cp.async.wait_group 0;\n");
        }
        __syncthreads();

        const float* Ksb = sK + (t & 1) * 8704;
        float acc[4][4][4];
        #pragma unroll
        for (int i = 0; i < 4; ++i)
            #pragma unroll
            for (int j = 0; j < 4; ++j)
                #pragma unroll
                for (int r = 0; r < 4; ++r) acc[i][j][r] = 0.0f;

        #pragma unroll
        for (int kk = 0; kk < 8; ++kk) {
            const int kb = kk * 8;
            uint32_t a[4][4], b[4][2];
            #pragma unroll
            for (int i = 0; i < 4; ++i) {
                a[i][0] = cvt_u(sQ[(wm0 + 16*i + g    ) * 68 + kb + q    ]);
                a[i][1] = cvt_u(sQ[(wm0 + 16*i + g + 8) * 68 + kb + q    ]);
                a[i][2] = cvt_u(sQ[(wm0 + 16*i + g    ) * 68 + kb + q + 4]);
                a[i][3] = cvt_u(sQ[(wm0 + 16*i + g + 8) * 68 + kb + q + 4]);
            }
            #pragma unroll
            for (int j = 0; j < 4; ++j) {
                b[j][0] = cvt_u(Ksb[(wn0 + 8*j + g) * 68 + kb + q    ]);
                b[j][1] = cvt_u(Ksb[(wn0 + 8*j + g) * 68 + kb + q + 4]);
            }
            #pragma unroll
            for (int i = 0; i < 4; ++i)
                #pragma unroll
                for (int j = 0; j < 4; ++j)
                    MMA_TF32(acc[i][j], a[i], b[j]);
        }
        __syncthreads();

        // issue load for tile t+2 into the freed buffer
        if (t + 2 < 4) {
            const int dst = (t & 1) * 8704;
            #pragma unroll
            for (int it = 0; it < 8; ++it) {
                const int idx = tid + it * 256;
                const int r = idx >> 4, c4 = (idx & 15) << 2;
                CP16(sKa + (uint32_t)(dst + r * 68 + c4) * 4,
                     &Kz[(size_t)(cg0 + (t + 2) * 128 + r) * DH + c4]);
            }
            asm volatile("cp.async.commit_group;\n");
        }

        // Epilogue: e = exp(0.125*s) * maskbit; write; accumulate sum
        const int colb = cg0 + t * 128 + wn0;
        const int wword = colb >> 5;
        #pragma unroll
        for (int i = 0; i < 4; ++i) {
            #pragma unroll
            for (int rr = 0; rr < 2; ++rr) {
                const int gr = row0 + wm0 + 16*i + g + rr*8;
                const uint32_t mw = mrow0[(size_t)gr * (SS/32) + wword];
                float sacc = 0.0f;
                #pragma unroll
                for (int j = 0; j < 4; ++j) {
                    const int cl = 8*j + 2*q;
                    float e0 = __expf(acc[i][j][rr*2    ] * 0.125f)
                             * (float)((mw >> cl) & 1u);
                    float e1 = __expf(acc[i][j][rr*2 + 1] * 0.125f)
                             * (float)((mw >> (cl+1)) & 1u);
                    *(float2*)&Cz[(size_t)gr * SS + colb + cl] = make_float2(e0, e1);
                    sacc += e0 + e1;
                }
                s8[i][rr] += sacc;
            }
        }
    }

    // reduce sums: across q lanes, then 4 col-warps
    #pragma unroll
    for (int i = 0; i < 4; ++i) {
        #pragma unroll
        for (int rr = 0; rr < 2; ++rr) {
            float s = s8[i][rr];
            s += __shfl_xor_sync(0xffffffffu, s, 1);
            s += __shfl_xor_sync(0xffffffffu, s, 2);
            if (q == 0) {
                const int R = wm0 + 16*i + g + rr*8;
                red_s[R * 4 + wc] = s;
            }
        }
    }
    __syncthreads();
    if (tid < 128) {
        float s = red_s[tid * 4] + red_s[tid * 4 + 1]
                + red_s[tid * 4 + 2] + red_s[tid * 4 + 3];
        Part[((size_t)z * SS + row0 + tid) * 4 + blockIdx.x] = s;
    }
}

// ---------------------------------------------------------------------------
// Reduce partials -> per-row 1/sum
// ---------------------------------------------------------------------------
__global__ __launch_bounds__(256)
void reduce_stats(const float* __restrict__ Part, float* __restrict__ InvS)
{
    const int row = blockIdx.x * 256 + threadIdx.x;
    float4 p = *(const float4*)&Part[(size_t)row * 4];
    float S = p.x + p.y + p.z + p.w;
    InvS[row] = (S > 0.0f) ? 1.0f / S : 0.0f;
}

// ---------------------------------------------------------------------------
// AV fused with normalization: 512 threads, KT=64 per iter (32 iters,
// 1 sync/iter). Reads unnormalized e, w = e*invS (one FMUL), writes
// weights in place (per-thread RMW of its own addresses -> race-free),
// accumulates W@V. Warp tile 32x16 (4x4 warp grid).
// ---------------------------------------------------------------------------
#define AV_SMEM_FLOATS (2*8704 + 2*4352 + 128)

__global__ __launch_bounds__(512, 1)
void mma_av(float* __restrict__ Wts, const float* __restrict__ Vh,
            const float* __restrict__ InvS, float* __restrict__ Ctx)
{
    extern __shared__ float sm[];
    float* As = sm;                    // [2][128][68]
    float* Bs = sm + 2 * 8704;         // [2][64][68]
    float* sI = sm + 2 * 8704 + 2 * 4352;   // [128]

    const int z = blockIdx.y;
    float* Aw = Wts + (size_t)z * SS * SS;
    const float* Vv = Vh + (size_t)z * SS * DH;
    const int row0 = blockIdx.x * 128;

    const int tid = threadIdx.x;
    const int wid = tid >> 5, lane = tid & 31;
    const int g = lane >> 2, q = lane & 3;
    const int wm0 = (wid >> 2) * 32;
    const int wn0 = (wid & 3) * 16;

    if (tid < 128)
        sI[tid] = InvS[(size_t)z * SS + row0 + tid];

    float acc[2][2][4];
    #pragma unroll
    for (int i = 0; i < 2; ++i)
        #pragma unroll
        for (int j = 0; j < 2; ++j)
            #pragma unroll
            for (int r = 0; r < 4; ++r) acc[i][j][r] = 0.0f;

    // prologue loads (tile 0): A 128x64, V 64x64
    float4 ra[4], rb[2];
    #pragma unroll
    for (int it = 0; it < 4; ++it) {
        const int idx = tid + it * 512;
        const int r = idx >> 4, c4 = (idx & 15) << 2;
        ra[it] = *(const float4*)&Aw[(size_t)(row0 + r) * SS + c4];
    }
    #pragma unroll
    for (int it = 0; it < 2; ++it) {
        const int idx = tid + it * 512;
        const int r = idx >> 4, c4 = (idx & 15) << 2;
        rb[it] = *(const float4*)&Vv[(size_t)r * DH + c4];
    }
    __syncthreads();   // sI visible

    for (int t = 0; t < SS / 64; ++t) {
        const int kt = t * 64;
        const int st = t & 1;
        #pragma unroll
        for (int it = 0; it < 4; ++it) {
            const int idx = tid + it * 512;
            const int r = idx >> 4, c4 = (idx & 15) << 2;
            const float I = sI[r];
            float4 w;
            w.x = ra[it].x * I;
            w.y = ra[it].y * I;
            w.z = ra[it].z * I;
            w.w = ra[it].w * I;
            *(float4*)&Aw[(size_t)(row0 + r) * SS + kt + c4] = w;   // final weights
            *(float4*)&As[st * 8704 + r * 68 + c4] =
                make_float4(to_tf32(w.x), to_tf32(w.y), to_tf32(w.z), to_tf32(w.w));
        }
        #pragma unroll
        for (int it = 0; it < 2; ++it) {
            const int idx = tid + it * 512;
            const int r = idx >> 4, c4 = (idx & 15) << 2;
            *(float4*)&Bs[st * 4352 + r * 68 + c4] =
                make_float4(to_tf32(rb[it].x), to_tf32(rb[it].y),
                            to_tf32(rb[it].z), to_tf32(rb[it].w));
        }
        __syncthreads();
        if (t + 1 < SS / 64) {
            const int kt2 = kt + 64;
            #pragma unroll
            for (int it = 0; it < 4; ++it) {
                const int idx = tid + it * 512;
                const int r = idx >> 4, c4 = (idx & 15) << 2;
                ra[it] = *(const float4*)&Aw[(size_t)(row0 + r) * SS + kt2 + c4];
            }
            #pragma unroll
            for (int it = 0; it < 2; ++it) {
                const int idx = tid + it * 512;
                const int r = idx >> 4, c4 = (idx & 15) << 2;
                rb[it] = *(const float4*)&Vv[(size_t)(kt2 + r) * DH + c4];
            }
        }
        const float* Asb = As + st * 8704;
        const float* Bsb = Bs + st * 4352;
        #pragma unroll
        for (int kk = 0; kk < 8; ++kk) {
            const int kb = kk * 8;
            uint32_t a[2][4], b[2][2];
            #pragma unroll
            for (int i = 0; i < 2; ++i) {
                a[i][0] = __float_as_uint(Asb[(wm0 + 16*i + g    ) * 68 + kb + q    ]);
                a[i][1] = __float_as_uint(Asb[(wm0 + 16*i + g + 8) * 68 + kb + q    ]);
                a[i][2] = __float_as_uint(Asb[(wm0 + 16*i + g    ) * 68 + kb + q + 4]);
                a[i][3] = __float_as_uint(Asb[(wm0 + 16*i + g + 8) * 68 + kb + q + 4]);
            }
            #pragma unroll
            for (int j = 0; j < 2; ++j) {
                b[j][0] = __float_as_uint(Bsb[(kb + q    ) * 68 + wn0 + 8*j + g]);
                b[j][1] = __float_as_uint(Bsb[(kb + q + 4) * 68 + wn0 + 8*j + g]);
            }
            #pragma unroll
            for (int i = 0; i < 2; ++i)
                #pragma unroll
                for (int j = 0; j < 2; ++j)
                    MMA_TF32(acc[i][j], a[i], b[j]);
        }
        __syncthreads();
    }

    const int b = z / HH, h = z % HH;
    #pragma unroll
    for (int i = 0; i < 2; ++i) {
        #pragma unroll
        for (int rr = 0; rr < 2; ++rr) {
            const int s = row0 + wm0 + 16*i + g + rr*8;
            #pragma unroll
            for (int j = 0; j < 2; ++j) {
                const int n = wn0 + 8*j + 2*q;
                *(float2*)&Ctx[((size_t)(b*SS + s))*DD + h*64 + n] =
                    make_float2(acc[i][j][rr*2], acc[i][j][rr*2 + 1]);
            }
        }
    }
}

// ---------------------------------------------------------------------------
extern "C" void kernel_launch(void* const* d_in, const int* in_sizes, int n_in,
                              void* d_out, int out_size)
{
    const float* q       = (const float*)d_in[0];
    const float* k       = (const float*)d_in[1];
    const float* v       = (const float*)d_in[2];
    const int*   mask    = (const int*)d_in[3];
    const float* wq_w    = (const float*)d_in[4];
    const float* wq_b    = (const float*)d_in[5];
    const float* wk_w    = (const float*)d_in[6];
    const float* wk_b    = (const float*)d_in[7];
    const float* wv_w    = (const float*)d_in[8];
    const float* wv_b    = (const float*)d_in[9];
    const float* dense_w = (const float*)d_in[10];
    const float* dense_b = (const float*)d_in[11];

    float* out = (float*)d_out;
    float* wts = out + (size_t)BB * SS * DD;

    void *pQ, *pK, *pV, *pC, *pP, *pS, *pM;
    cudaGetSymbolAddress(&pQ, g_Q);
    cudaGetSymbolAddress(&pK, g_K);
    cudaGetSymbolAddress(&pV, g_V);
    cudaGetSymbolAddress(&pC, g_Ctx);
    cudaGetSymbolAddress(&pP, g_Part);
    cudaGetSymbolAddress(&pS, g_InvS);
    cudaGetSymbolAddress(&pM, g_MaskBits);
    float*    gQ = (float*)pQ;
    float*    gK = (float*)pK;
    float*    gV = (float*)pV;
    float*    gC = (float*)pC;
    float*    gP = (float*)pP;
    float*    gS = (float*)pS;
    uint32_t* gM = (uint32_t*)pM;

    const int SM_GEMM = 73728;
    const int SM_SC   = SC_SMEM_FLOATS * 4;
    const int SM_AV   = AV_SMEM_FLOATS * 4;

    static cudaStream_t s1;
    static cudaEvent_t evRoot, evM, evV;
    static int inited = 0;
    if (!inited) {
        cudaFuncSetAttribute(mma_nt<0>, cudaFuncAttributeMaxDynamicSharedMemorySize, SM_GEMM);
        cudaFuncSetAttribute(mma_nt<1>, cudaFuncAttributeMaxDynamicSharedMemorySize, SM_GEMM);
        cudaFuncSetAttribute(scores_kernel, cudaFuncAttributeMaxDynamicSharedMemorySize, SM_SC);
        cudaFuncSetAttribute(mma_av, cudaFuncAttributeMaxDynamicSharedMemorySize, SM_AV);
        cudaStreamCreateWithFlags(&s1, cudaStreamNonBlocking);
        cudaEventCreateWithFlags(&evRoot, cudaEventDisableTiming);
        cudaEventCreateWithFlags(&evM, cudaEventDisableTiming);
        cudaEventCreateWithFlags(&evV, cudaEventDisableTiming);
        inited = 1;
    }

    const dim3 blk(256);

    // Fork side stream off the capture origin
    cudaEventRecord(evRoot, 0);
    cudaStreamWaitEvent(s1, evRoot, 0);

    // side stream: maskbits, then V projection
    maskbits_kernel<<<NWORDS / 256, 256, 0, s1>>>(mask, gM);
    cudaEventRecord(evM, s1);
    {
        ProjArgs pv;
        pv.A[0] = v;  pv.W[0] = wv_w;  pv.bias[0] = wv_b;  pv.C[0] = gV;
        pv.A[1] = pv.A[2] = v; pv.W[1] = pv.W[2] = wv_w;
        pv.bias[1] = pv.bias[2] = wv_b; pv.C[1] = pv.C[2] = gV;
        const dim3 gpv(DD / 128, MROWS / 128, 1);
        mma_nt<0><<<gpv, blk, SM_GEMM, s1>>>(pv);
    }
    cudaEventRecord(evV, s1);

    // default stream: Q,K projections (z=2)
    {
        ProjArgs pqk;
        pqk.A[0] = q;  pqk.W[0] = wq_w;  pqk.bias[0] = wq_b;  pqk.C[0] = gQ;
        pqk.A[1] = k;  pqk.W[1] = wk_w;  pqk.bias[1] = wk_b;  pqk.C[1] = gK;
        pqk.A[2] = q;  pqk.W[2] = wq_w;  pqk.bias[2] = wq_b;  pqk.C[2] = gQ;
        const dim3 gqk(DD / 128, MROWS / 128, 2);
        mma_nt<0><<<gqk, blk, SM_GEMM>>>(pqk);
    }

    // scores needs maskbits
    cudaStreamWaitEvent(0, evM, 0);
    const dim3 gsc(SS / 512, SS / 128, BH);           // (4, 16, 32)
    scores_kernel<<<gsc, blk, SM_SC>>>(gQ, gK, gM, wts, gP);

    reduce_stats<<<NROWTOT / 256, 256>>>(gP, gS);

    // mma_av needs V projection
    cudaStreamWaitEvent(0, evV, 0);
    const dim3 gav(SS / 128, BH, 1);                  // (16, 32)
    mma_av<<<gav, 512, SM_AV>>>(wts, gV, gS, gC);

    // dense
    {
        ProjArgs da;
        da.A[0] = gC; da.W[0] = dense_w; da.bias[0] = dense_b; da.C[0] = out;
        da.A[1] = da.A[2] = gC; da.W[1] = da.W[2] = dense_w;
        da.bias[1] = da.bias[2] = dense_b; da.C[1] = da.C[2] = out;
        const dim3 gd(DD / 128, MROWS / 128, 1);
        mma_nt<1><<<gd, blk, SM_GEMM>>>(da);
    }
}